// round 4
// baseline (speedup 1.0000x reference)
#include <cuda_runtime.h>
#include <math.h>

#define BB 8
#define NN 2048
#define BN 16384
#define INCH 16
#define HIDD 128
#define CC 64
#define EE 262144

// ---------------- scratch ----------------
__device__ float g_xw1[BN * HIDD];
__device__ float g_h1[BN * HIDD];
__device__ float g_xw2[BN * HIDD];
__device__ float g_h2[BN * HIDD];
__device__ float g_s[BN * CC];
__device__ float g_AS[BN * CC];
__device__ float g_dis[BN];
__device__ float g_degf[BN];
__device__ int   g_cnt_dst[BN];
__device__ int   g_cnt_src[BN];
__device__ int   g_cnt_d2[BN];
__device__ int   g_cur_dst[BN];
__device__ int   g_cur_src[BN];
__device__ int   g_off_dst[BN + 1];
__device__ int   g_off_src[BN + 1];
__device__ int   g_e_by_dst[EE];
__device__ int   g_e_by_src[EE];
__device__ int   g_knn[BN * 4];
__device__ float g_outadj[BB * CC * CC];
__device__ float g_ssm[BB * CC * CC];
__device__ float g_pool[BB * CC * HIDD];
__device__ float g_ca[BB * CC];
__device__ float g_colsum[BB * CC];

// ---------------- init ----------------
__global__ void k_init() {
    int i = blockIdx.x * blockDim.x + threadIdx.x;
    int st = gridDim.x * blockDim.x;
    for (int k = i; k < BN; k += st) {
        g_cnt_dst[k] = 0; g_cnt_src[k] = 0; g_cnt_d2[k] = 0;
        g_cur_dst[k] = 0; g_cur_src[k] = 0;
    }
    for (int k = i; k < BB * CC * CC; k += st) { g_outadj[k] = 0.f; g_ssm[k] = 0.f; }
    for (int k = i; k < BB * CC * HIDD; k += st) g_pool[k] = 0.f;
}

// ---------------- edge counting ----------------
__global__ void k_count(const int* __restrict__ esrc, const int* __restrict__ edst) {
    int e = blockIdx.x * blockDim.x + threadIdx.x;
    if (e >= EE) return;
    int s = esrc[e], d = edst[e];
    atomicAdd(&g_cnt_dst[d], 1);
    atomicAdd(&g_cnt_src[s], 1);
    int d2 = (s / NN) * NN + (d % NN);     // DMoN adj column node
    atomicAdd(&g_cnt_d2[d2], 1);
}

// exclusive scan of 16384 ints; block 0 -> dst CSR, block 1 -> src CSR
__global__ void k_scan() {
    __shared__ int part[1024];
    const int* cnt = (blockIdx.x == 0) ? g_cnt_dst : g_cnt_src;
    int* off = (blockIdx.x == 0) ? g_off_dst : g_off_src;
    int t = threadIdx.x;
    int base = t * 16;
    int loc[16]; int s = 0;
#pragma unroll
    for (int i = 0; i < 16; i++) { loc[i] = s; s += cnt[base + i]; }
    part[t] = s; __syncthreads();
    for (int d = 1; d < 1024; d <<= 1) {
        int v = (t >= d) ? part[t - d] : 0;
        __syncthreads();
        part[t] += v;
        __syncthreads();
    }
    int pre = t ? part[t - 1] : 0;
#pragma unroll
    for (int i = 0; i < 16; i++) off[base + i] = pre + loc[i];
    if (t == 1023) off[BN] = part[1023];
}

__global__ void k_nodeprep() {
    int n = blockIdx.x * blockDim.x + threadIdx.x;
    if (n < BN) {
        g_dis[n] = rsqrtf((float)(g_cnt_dst[n] + 1));
        g_degf[n] = (float)g_cnt_d2[n];
    }
}

__global__ void k_fill(const int* __restrict__ esrc, const int* __restrict__ edst) {
    int e = blockIdx.x * blockDim.x + threadIdx.x;
    if (e >= EE) return;
    int s = esrc[e], d = edst[e];
    int p = g_off_dst[d] + atomicAdd(&g_cur_dst[d], 1);
    g_e_by_dst[p] = s;
    int d2 = (s / NN) * NN + (d % NN);
    int q = g_off_src[s] + atomicAdd(&g_cur_src[s], 1);
    g_e_by_src[q] = d2;
}

// per-bin insertion sort -> deterministic summation order
__global__ void k_sort() {
    int n = blockIdx.x * blockDim.x + threadIdx.x;
    if (n >= BN) return;
    {
        int beg = g_off_dst[n], end = g_off_dst[n + 1];
        for (int i = beg + 1; i < end; i++) {
            int v = g_e_by_dst[i], j = i - 1;
            while (j >= beg && g_e_by_dst[j] > v) { g_e_by_dst[j + 1] = g_e_by_dst[j]; j--; }
            g_e_by_dst[j + 1] = v;
        }
    }
    {
        int beg = g_off_src[n], end = g_off_src[n + 1];
        for (int i = beg + 1; i < end; i++) {
            int v = g_e_by_src[i], j = i - 1;
            while (j >= beg && g_e_by_src[j] > v) { g_e_by_src[j + 1] = g_e_by_src[j]; j--; }
            g_e_by_src[j + 1] = v;
        }
    }
}

// ---------------- tiled GEMM: C[M,Nc] = A[M,K] @ W[K,Nc], tile 64x64, BK=16 ----------------
__device__ __forceinline__ void gemm_body(const float* __restrict__ A,
                                          const float* __restrict__ W,
                                          float* __restrict__ Cc, int K, int Nc) {
    __shared__ float As[16][64];
    __shared__ float Bs[16][64];
    int tid = threadIdx.x;
    int bx = blockIdx.x, by = blockIdx.y;
    int tx = tid & 15, ty = tid >> 4;
    float acc[4][4];
#pragma unroll
    for (int i = 0; i < 4; i++)
#pragma unroll
        for (int j = 0; j < 4; j++) acc[i][j] = 0.f;
    int arow = tid >> 2, acol = (tid & 3) << 2;
    int brow = tid >> 4, bcol = (tid & 15) << 2;
    const float* Ap = A + (size_t)(by * 64 + arow) * K + acol;
    const float* Wq = W + (size_t)brow * Nc + bx * 64 + bcol;
    for (int kt = 0; kt < K; kt += 16) {
        float4 av = *(const float4*)(Ap + kt);
        float4 bv = *(const float4*)(Wq + (size_t)kt * Nc);
        As[acol + 0][arow] = av.x; As[acol + 1][arow] = av.y;
        As[acol + 2][arow] = av.z; As[acol + 3][arow] = av.w;
        *(float4*)&Bs[brow][bcol] = bv;
        __syncthreads();
#pragma unroll
        for (int kk = 0; kk < 16; kk++) {
            float4 a = *(const float4*)&As[kk][ty << 2];
            float4 b = *(const float4*)&Bs[kk][tx << 2];
            float aa[4] = {a.x, a.y, a.z, a.w};
            float bb[4] = {b.x, b.y, b.z, b.w};
#pragma unroll
            for (int i = 0; i < 4; i++)
#pragma unroll
                for (int j = 0; j < 4; j++) acc[i][j] += aa[i] * bb[j];
        }
        __syncthreads();
    }
#pragma unroll
    for (int i = 0; i < 4; i++) {
        float4 v = make_float4(acc[i][0], acc[i][1], acc[i][2], acc[i][3]);
        *(float4*)(Cc + (size_t)(by * 64 + (ty << 2) + i) * Nc + bx * 64 + (tx << 2)) = v;
    }
}

__global__ void k_gemm1(const float* __restrict__ x, const float* __restrict__ W1) {
    gemm_body(x, W1, g_xw1, INCH, HIDD);
}
__global__ void k_gemm2(const float* __restrict__ W2) {
    gemm_body(g_h1, W2, g_xw2, HIDD, HIDD);
}
__global__ void k_gemm3(const float* __restrict__ Wp) {
    gemm_body(g_h2, Wp, g_s, HIDD, CC);
}

// ---------------- GCN1: CSR gather + self loop + bias + relu ----------------
__global__ void k_gcn1(const float* __restrict__ b1) {
    int n = blockIdx.x, t = threadIdx.x;
    int beg = g_off_dst[n], end = g_off_dst[n + 1];
    float dn = g_dis[n];
    float acc = g_xw1[(size_t)n * HIDD + t] * (dn * dn);
    for (int e = beg; e < end; e++) {
        int s = g_e_by_dst[e];
        acc += g_xw1[(size_t)s * HIDD + t] * (g_dis[s] * dn);
    }
    float v = acc + b1[t];
    g_h1[(size_t)n * HIDD + t] = v > 0.f ? v : 0.f;
}

// ---------------- KNN brute force, k=4, lowest-index tie-break ----------------
__global__ void k_knn() {
    __shared__ float4 crd[NN];
    __shared__ float md[256 * 4];
    __shared__ int   mi[256 * 4];
    int b = blockIdx.x >> 5;           // 32 blocks / graph
    int chunk = blockIdx.x & 31;       // 64 queries / block
    int tid = threadIdx.x;
    int gbase = b * NN;
    for (int j = tid; j < NN; j += 256) {
        const float* r = g_h1 + (size_t)(gbase + j) * HIDD;
        crd[j] = make_float4(r[0], r[1], r[2], 0.f);
    }
    __syncthreads();
    int ql = tid & 63;
    int sp = tid >> 6;                 // 4 splits x 512 candidates
    int qi = chunk * 64 + ql;
    float4 q = crd[qi];
    float b0 = 3.0e38f, b1 = 3.0e38f, b2 = 3.0e38f, b3 = 3.0e38f;
    int i0 = -1, i1 = -1, i2 = -1, i3 = -1;
    int j0 = sp * 512, j1 = j0 + 512;
    for (int j = j0; j < j1; j++) {
        float4 p = crd[j];
        float dx = q.x - p.x, dy = q.y - p.y, dz = q.z - p.z;
        float d2 = __fadd_rn(__fadd_rn(__fmul_rn(dx, dx), __fmul_rn(dy, dy)),
                             __fmul_rn(dz, dz));
        if (d2 < b3 && j != qi) {
            if (d2 < b1) {
                b3 = b2; i3 = i2; b2 = b1; i2 = i1;
                if (d2 < b0) { b1 = b0; i1 = i0; b0 = d2; i0 = j; }
                else { b1 = d2; i1 = j; }
            } else {
                if (d2 < b2) { b3 = b2; i3 = i2; b2 = d2; i2 = j; }
                else { b3 = d2; i3 = j; }
            }
        }
    }
    md[tid * 4 + 0] = b0; md[tid * 4 + 1] = b1; md[tid * 4 + 2] = b2; md[tid * 4 + 3] = b3;
    mi[tid * 4 + 0] = i0; mi[tid * 4 + 1] = i1; mi[tid * 4 + 2] = i2; mi[tid * 4 + 3] = i3;
    __syncthreads();
    if (sp == 0) {
        int res[4];
        for (int r = 0; r < 4; r++) {
            float bd = 3.4e38f; int bi = 0x7fffffff; int bloc = -1;
            for (int s2 = 0; s2 < 4; s2++) {
                int base2 = (s2 * 64 + ql) * 4;
#pragma unroll
                for (int k = 0; k < 4; k++) {
                    float d = md[base2 + k]; int ii = mi[base2 + k];
                    if (d < bd || (d == bd && ii < bi)) { bd = d; bi = ii; bloc = base2 + k; }
                }
            }
            md[bloc] = 3.4e38f;
            res[r] = bi;
        }
        int4 o = make_int4(gbase + res[0], gbase + res[1], gbase + res[2], gbase + res[3]);
        *(int4*)&g_knn[(size_t)(gbase + qi) * 4] = o;
    }
}

// ---------------- GCN2: uniform degree 5, norm = 0.2 ----------------
__global__ void k_gcn2(const float* __restrict__ b2) {
    int n = blockIdx.x, t = threadIdx.x;
    int4 nb = *(const int4*)&g_knn[(size_t)n * 4];
    float acc = g_xw2[(size_t)n * HIDD + t]
              + g_xw2[(size_t)nb.x * HIDD + t]
              + g_xw2[(size_t)nb.y * HIDD + t]
              + g_xw2[(size_t)nb.z * HIDD + t]
              + g_xw2[(size_t)nb.w * HIDD + t];
    float v = acc * 0.2f + b2[t];
    g_h2[(size_t)n * HIDD + t] = v > 0.f ? v : 0.f;
}

// ---------------- softmax over C=64 ----------------
__global__ void k_softmax(const float* __restrict__ bp) {
    __shared__ float sh[64];
    int n = blockIdx.x, t = threadIdx.x;
    float l = g_s[(size_t)n * CC + t] + bp[t];
    sh[t] = l; __syncthreads();
    for (int s = 32; s > 0; s >>= 1) { if (t < s) sh[t] = fmaxf(sh[t], sh[t + s]); __syncthreads(); }
    float mx = sh[0]; __syncthreads();
    float e = expf(l - mx);
    sh[t] = e; __syncthreads();
    for (int s = 32; s > 0; s >>= 1) { if (t < s) sh[t] += sh[t + s]; __syncthreads(); }
    g_s[(size_t)n * CC + t] = e / sh[0];
}

// ---------------- AS[i,:] = sum_{edges src=i} s[colnode,:] ----------------
__global__ void k_asgather() {
    int n = blockIdx.x, t = threadIdx.x;
    int beg = g_off_src[n], end = g_off_src[n + 1];
    float acc = 0.f;
    for (int e = beg; e < end; e++) {
        int j = g_e_by_src[e];
        acc += g_s[(size_t)j * CC + t];
    }
    g_AS[(size_t)n * CC + t] = acc;
}

// ---------------- fused per-graph: out_adj = S^T AS, ss = S^T S, pool = S^T X ----------------
__global__ void k_reduce1() {
    __shared__ float sS[4][64], sA[4][64], sX[4][128];
    int b = blockIdx.x >> 3;
    int chunk = blockIdx.x & 7;        // 256 nodes per chunk
    int tid = threadIdx.x;
    int c = tid >> 2, qq = tid & 3;
    int d0 = qq * 16, f0 = qq * 32;
    float aoa[16], ass[16], aout[32];
#pragma unroll
    for (int k = 0; k < 16; k++) { aoa[k] = 0.f; ass[k] = 0.f; }
#pragma unroll
    for (int k = 0; k < 32; k++) aout[k] = 0.f;
    int node0 = b * NN + chunk * 256;
    for (int nb = 0; nb < 256; nb += 4) {
        {
            int nn2 = tid >> 6, cc2 = tid & 63;
            int node = node0 + nb + nn2;
            sS[nn2][cc2] = g_s[(size_t)node * CC + cc2];
            sA[nn2][cc2] = g_AS[(size_t)node * CC + cc2];
        }
        for (int u = tid; u < 4 * 128; u += 256) {
            int nn2 = u >> 7, ff = u & 127;
            int node = node0 + nb + nn2;
            sX[nn2][ff] = g_h2[(size_t)node * HIDD + ff];
        }
        __syncthreads();
#pragma unroll
        for (int nn2 = 0; nn2 < 4; nn2++) {
            float sa = sS[nn2][c];
#pragma unroll
            for (int k = 0; k < 16; k++) {
                aoa[k] += sa * sA[nn2][d0 + k];
                ass[k] += sa * sS[nn2][d0 + k];
            }
#pragma unroll
            for (int k = 0; k < 32; k++) aout[k] += sa * sX[nn2][f0 + k];
        }
        __syncthreads();
    }
#pragma unroll
    for (int k = 0; k < 16; k++) {
        atomicAdd(&g_outadj[b * CC * CC + c * CC + d0 + k], aoa[k]);
        atomicAdd(&g_ssm[b * CC * CC + c * CC + d0 + k], ass[k]);
    }
#pragma unroll
    for (int k = 0; k < 32; k++)
        atomicAdd(&g_pool[b * CC * HIDD + c * HIDD + f0 + k], aout[k]);
}

// ---------------- ca / column sums ----------------
__global__ void k_ca() {
    int b = blockIdx.x, c = threadIdx.x;
    float ca = 0.f, cs = 0.f;
#pragma unroll 4
    for (int n = 0; n < NN; n++) {
        float sv = g_s[(size_t)(b * NN + n) * CC + c];
        float dg = g_degf[b * NN + n];
        ca += sv * dg; cs += sv;
    }
    g_ca[b * CC + c] = ca;
    g_colsum[b * CC + c] = cs;
}

// ---------------- losses ----------------
__device__ __forceinline__ float blockReduceSum256(float v, float* sh) {
    sh[threadIdx.x] = v; __syncthreads();
    for (int s = 128; s > 0; s >>= 1) {
        if (threadIdx.x < s) sh[threadIdx.x] += sh[threadIdx.x + s];
        __syncthreads();
    }
    float r = sh[0]; __syncthreads();
    return r;
}

__global__ void k_loss(float* __restrict__ dout, int limit) {
    __shared__ float sh[256];
    int t = threadIdx.x;
    float tot = 0.f;
    for (int b = 0; b < BB; b++) {
        const float* ss = g_ssm + b * CC * CC;
        const float* oa = g_outadj + b * CC * CC;
        float v = 0.f;
        for (int i = t; i < CC * CC; i += 256) { float w = ss[i]; v += w * w; }
        float fro = sqrtf(blockReduceSum256(v, sh));
        v = 0.f;
        for (int i = t; i < CC * CC; i += 256) {
            float w = ss[i] / fro - ((i % (CC + 1)) == 0 ? 0.125f : 0.f);
            v += w * w;
        }
        float ortho_b = sqrtf(blockReduceSum256(v, sh));
        v = (t < CC) ? oa[t * (CC + 1)] : 0.f;
        float tr = blockReduceSum256(v, sh);
        v = (t < CC) ? g_ca[b * CC + t] * g_ca[b * CC + t] : 0.f;
        float ca2 = blockReduceSum256(v, sh);
        v = (t < CC) ? g_colsum[b * CC + t] * g_colsum[b * CC + t] : 0.f;
        float cs2 = blockReduceSum256(v, sh);
        v = 0.f;
        for (int n = t; n < NN; n += 256) v += g_degf[b * NN + n];
        float twom = blockReduceSum256(v, sh);
        float spectral_b = -(tr - ca2 / twom) / twom;
        float cluster_b = sqrtf(cs2) / (float)NN * 8.0f - 1.0f;
        tot += spectral_b + ortho_b + cluster_b;
    }
    if (t == 0 && 65536 < limit) dout[65536] = tot * 0.125f;
}

// ---------------- selu + log_softmax over F=128 ----------------
__global__ void k_selulsm(float* __restrict__ dout, int limit) {
    __shared__ float sh[128];
    int row = blockIdx.x, t = threadIdx.x;
    float v = g_pool[(size_t)row * HIDD + t];
    const float SC = 1.0507009873554805f, AL = 1.6732632423543772f;
    float y = v > 0.f ? SC * v : SC * (AL * expm1f(v));
    sh[t] = y; __syncthreads();
    for (int s = 64; s > 0; s >>= 1) { if (t < s) sh[t] = fmaxf(sh[t], sh[t + s]); __syncthreads(); }
    float mx = sh[0]; __syncthreads();
    float e = expf(y - mx);
    sh[t] = e; __syncthreads();
    for (int s = 64; s > 0; s >>= 1) { if (t < s) sh[t] += sh[t + s]; __syncthreads(); }
    float lse = logf(sh[0]);
    int idx = row * HIDD + t;
    if (idx < limit) dout[idx] = y - mx - lse;
}

__global__ void k_copys(float* __restrict__ dout, int limit) {
    int i = blockIdx.x * blockDim.x + threadIdx.x;
    if (i < BN * CC && 65537 + i < limit) dout[65537 + i] = g_s[i];
}

// ---------------- launcher ----------------
extern "C" void kernel_launch(void* const* d_in, const int* in_sizes, int n_in,
                              void* d_out, int out_size) {
    const float* x    = (const float*)d_in[0];
    const int*   esrc = (const int*)d_in[1];
    const int*   edst = (const int*)d_in[2];
    // d_in[3] = batch (unused)
    const float* W1 = (const float*)d_in[4];
    const float* b1 = (const float*)d_in[5];
    const float* W2 = (const float*)d_in[6];
    const float* b2 = (const float*)d_in[7];
    const float* Wp = (const float*)d_in[8];
    const float* bp = (const float*)d_in[9];
    float* out = (float*)d_out;

    k_init<<<256, 256>>>();
    k_count<<<EE / 256, 256>>>(esrc, edst);
    k_scan<<<2, 1024>>>();
    k_nodeprep<<<BN / 256, 256>>>();
    k_fill<<<EE / 256, 256>>>(esrc, edst);
    k_sort<<<BN / 128, 128>>>();
    k_gemm1<<<dim3(2, 256), 256>>>(x, W1);
    k_gcn1<<<BN, 128>>>(b1);
    k_knn<<<256, 256>>>();
    k_gemm2<<<dim3(2, 256), 256>>>(W2);
    k_gcn2<<<BN, 128>>>(b2);
    k_gemm3<<<dim3(1, 256), 256>>>(Wp);
    k_softmax<<<BN, 64>>>(bp);
    k_asgather<<<BN, 64>>>();
    k_reduce1<<<64, 256>>>();
    k_ca<<<BB, 64>>>();
    k_loss<<<1, 256>>>(out, out_size);
    k_selulsm<<<BB * CC, 128>>>(out, out_size);
    k_copys<<<(BN * CC + 255) / 256, 256>>>(out, out_size);
}

// round 6
// speedup vs baseline: 1.6873x; 1.6873x over previous
#include <cuda_runtime.h>
#include <math.h>

#define BB 8
#define NN 2048
#define BN 16384
#define INCH 16
#define HIDD 128
#define CC 64
#define EE 262144

// ---------------- scratch ----------------
__device__ float g_xw1[BN * HIDD];
__device__ float g_h1[BN * HIDD];
__device__ float g_xw2[BN * HIDD];
__device__ float g_h2[BN * HIDD];
__device__ float g_s[BN * CC];
__device__ float g_AS[BN * CC];
__device__ float g_dis[BN];
__device__ float g_degf[BN];
__device__ float g_negx[BN];
__device__ float g_negy[BN];
__device__ float g_negz[BN];
__device__ int   g_cnt_dst[BN];
__device__ int   g_cnt_src[BN];
__device__ int   g_cnt_d2[BN];
__device__ int   g_cur_dst[BN];
__device__ int   g_cur_src[BN];
__device__ int   g_off_dst[BN + 1];
__device__ int   g_off_src[BN + 1];
__device__ int   g_e_by_dst[EE];
__device__ int   g_e_by_src[EE];
__device__ int   g_knn[BN * 4];
__device__ float g_outadj[BB * CC * CC];
__device__ float g_ssm[BB * CC * CC];
__device__ float g_pool[BB * CC * HIDD];
__device__ float g_ca[BB * CC];
__device__ float g_colsum[BB * CC];
__device__ float g_lossb[BB];

// ---------------- packed f32x2 helpers (lane-wise IEEE rn, same rounding as scalar) ----
__device__ __forceinline__ unsigned long long pack2(float a, float b) {
    unsigned long long r;
    asm("mov.b64 %0, {%1, %2};" : "=l"(r) : "f"(a), "f"(b));
    return r;
}
__device__ __forceinline__ void unpack2(unsigned long long v, float& lo, float& hi) {
    asm("mov.b64 {%0, %1}, %2;" : "=f"(lo), "=f"(hi) : "l"(v));
}
__device__ __forceinline__ unsigned long long add2(unsigned long long a, unsigned long long b) {
    unsigned long long r;
    asm("add.rn.f32x2 %0, %1, %2;" : "=l"(r) : "l"(a), "l"(b));
    return r;
}
__device__ __forceinline__ unsigned long long mul2(unsigned long long a, unsigned long long b) {
    unsigned long long r;
    asm("mul.rn.f32x2 %0, %1, %2;" : "=l"(r) : "l"(a), "l"(b));
    return r;
}

// ---------------- init ----------------
__global__ void k_init() {
    int i = blockIdx.x * blockDim.x + threadIdx.x;
    int st = gridDim.x * blockDim.x;
    for (int k = i; k < BN; k += st) {
        g_cnt_dst[k] = 0; g_cnt_src[k] = 0; g_cnt_d2[k] = 0;
        g_cur_dst[k] = 0; g_cur_src[k] = 0;
    }
    for (int k = i; k < BB * CC * CC; k += st) { g_outadj[k] = 0.f; g_ssm[k] = 0.f; }
    for (int k = i; k < BB * CC * HIDD; k += st) g_pool[k] = 0.f;
    for (int k = i; k < BB * CC; k += st) { g_ca[k] = 0.f; g_colsum[k] = 0.f; }
}

// ---------------- edge counting ----------------
__global__ void k_count(const int* __restrict__ esrc, const int* __restrict__ edst) {
    int e = blockIdx.x * blockDim.x + threadIdx.x;
    if (e >= EE) return;
    int s = esrc[e], d = edst[e];
    atomicAdd(&g_cnt_dst[d], 1);
    atomicAdd(&g_cnt_src[s], 1);
    int d2 = (s / NN) * NN + (d % NN);     // DMoN adj column node
    atomicAdd(&g_cnt_d2[d2], 1);
}

// blocks 0/1: exclusive scans (dst CSR, src CSR).  block 2: nodeprep.
__global__ void k_scan() {
    if (blockIdx.x == 2) {
        int t = threadIdx.x;
        for (int n = t; n < BN; n += 1024) {
            g_dis[n] = rsqrtf((float)(g_cnt_dst[n] + 1));
            g_degf[n] = (float)g_cnt_d2[n];
        }
        return;
    }
    __shared__ int part[1024];
    const int* cnt = (blockIdx.x == 0) ? g_cnt_dst : g_cnt_src;
    int* off = (blockIdx.x == 0) ? g_off_dst : g_off_src;
    int t = threadIdx.x;
    int base = t * 16;
    int loc[16]; int s = 0;
#pragma unroll
    for (int i = 0; i < 16; i++) { loc[i] = s; s += cnt[base + i]; }
    part[t] = s; __syncthreads();
    for (int d = 1; d < 1024; d <<= 1) {
        int v = (t >= d) ? part[t - d] : 0;
        __syncthreads();
        part[t] += v;
        __syncthreads();
    }
    int pre = t ? part[t - 1] : 0;
#pragma unroll
    for (int i = 0; i < 16; i++) off[base + i] = pre + loc[i];
    if (t == 1023) off[BN] = part[1023];
}

__global__ void k_fill(const int* __restrict__ esrc, const int* __restrict__ edst) {
    int e = blockIdx.x * blockDim.x + threadIdx.x;
    if (e >= EE) return;
    int s = esrc[e], d = edst[e];
    int p = g_off_dst[d] + atomicAdd(&g_cur_dst[d], 1);
    g_e_by_dst[p] = s;
    int d2 = (s / NN) * NN + (d % NN);
    int q = g_off_src[s] + atomicAdd(&g_cur_src[s], 1);
    g_e_by_src[q] = d2;
}

// per-bin insertion sort -> deterministic summation order
__global__ void k_sort() {
    int n = blockIdx.x * blockDim.x + threadIdx.x;
    if (n >= BN) return;
    {
        int beg = g_off_dst[n], end = g_off_dst[n + 1];
        for (int i = beg + 1; i < end; i++) {
            int v = g_e_by_dst[i], j = i - 1;
            while (j >= beg && g_e_by_dst[j] > v) { g_e_by_dst[j + 1] = g_e_by_dst[j]; j--; }
            g_e_by_dst[j + 1] = v;
        }
    }
    {
        int beg = g_off_src[n], end = g_off_src[n + 1];
        for (int i = beg + 1; i < end; i++) {
            int v = g_e_by_src[i], j = i - 1;
            while (j >= beg && g_e_by_src[j] > v) { g_e_by_src[j + 1] = g_e_by_src[j]; j--; }
            g_e_by_src[j + 1] = v;
        }
    }
}

// ---------------- tiled GEMM: C[M,Nc] = A[M,K] @ W[K,Nc], tile 64x64, BK=16 ----------------
__device__ __forceinline__ void gemm_body(const float* __restrict__ A,
                                          const float* __restrict__ W,
                                          float* __restrict__ Cc, int K, int Nc) {
    __shared__ float As[16][64];
    __shared__ float Bs[16][64];
    int tid = threadIdx.x;
    int bx = blockIdx.x, by = blockIdx.y;
    int tx = tid & 15, ty = tid >> 4;
    float acc[4][4];
#pragma unroll
    for (int i = 0; i < 4; i++)
#pragma unroll
        for (int j = 0; j < 4; j++) acc[i][j] = 0.f;
    int arow = tid >> 2, acol = (tid & 3) << 2;
    int brow = tid >> 4, bcol = (tid & 15) << 2;
    const float* Ap = A + (size_t)(by * 64 + arow) * K + acol;
    const float* Wq = W + (size_t)brow * Nc + bx * 64 + bcol;
    for (int kt = 0; kt < K; kt += 16) {
        float4 av = *(const float4*)(Ap + kt);
        float4 bv = *(const float4*)(Wq + (size_t)kt * Nc);
        As[acol + 0][arow] = av.x; As[acol + 1][arow] = av.y;
        As[acol + 2][arow] = av.z; As[acol + 3][arow] = av.w;
        *(float4*)&Bs[brow][bcol] = bv;
        __syncthreads();
#pragma unroll
        for (int kk = 0; kk < 16; kk++) {
            float4 a = *(const float4*)&As[kk][ty << 2];
            float4 b = *(const float4*)&Bs[kk][tx << 2];
            float aa[4] = {a.x, a.y, a.z, a.w};
            float bb[4] = {b.x, b.y, b.z, b.w};
#pragma unroll
            for (int i = 0; i < 4; i++)
#pragma unroll
                for (int j = 0; j < 4; j++) acc[i][j] += aa[i] * bb[j];
        }
        __syncthreads();
    }
#pragma unroll
    for (int i = 0; i < 4; i++) {
        float4 v = make_float4(acc[i][0], acc[i][1], acc[i][2], acc[i][3]);
        *(float4*)(Cc + (size_t)(by * 64 + (ty << 2) + i) * Nc + bx * 64 + (tx << 2)) = v;
    }
}

__global__ void k_gemm1(const float* __restrict__ x, const float* __restrict__ W1) {
    gemm_body(x, W1, g_xw1, INCH, HIDD);
}
__global__ void k_gemm2(const float* __restrict__ W2) {
    gemm_body(g_h1, W2, g_xw2, HIDD, HIDD);
}
__global__ void k_gemm3(const float* __restrict__ Wp) {
    gemm_body(g_h2, Wp, g_s, HIDD, CC);
}

// ---------------- GCN1: CSR gather + self loop + bias + relu (+ SoA negated coords) ----
__global__ void k_gcn1(const float* __restrict__ b1) {
    int n = blockIdx.x, t = threadIdx.x;
    int beg = g_off_dst[n], end = g_off_dst[n + 1];
    float dn = g_dis[n];
    float acc = g_xw1[(size_t)n * HIDD + t] * (dn * dn);
    for (int e = beg; e < end; e++) {
        int s = g_e_by_dst[e];
        acc += g_xw1[(size_t)s * HIDD + t] * (g_dis[s] * dn);
    }
    float v = acc + b1[t];
    float r = v > 0.f ? v : 0.f;
    g_h1[(size_t)n * HIDD + t] = r;
    if (t == 0) g_negx[n] = -r;
    else if (t == 1) g_negy[n] = -r;
    else if (t == 2) g_negz[n] = -r;
}

// ---------------- KNN brute force, k=4, packed f32x2, lowest-index tie-break ----------------
__device__ __forceinline__ void ins4(float d2, int j,
                                     float& b0, float& b1, float& b2, float& b3,
                                     int& i0, int& i1, int& i2, int& i3) {
    if (d2 < b1) {
        b3 = b2; i3 = i2; b2 = b1; i2 = i1;
        if (d2 < b0) { b1 = b0; i1 = i0; b0 = d2; i0 = j; }
        else { b1 = d2; i1 = j; }
    } else {
        if (d2 < b2) { b3 = b2; i3 = i2; b2 = d2; i2 = j; }
        else { b3 = d2; i3 = j; }
    }
}

__global__ void k_knn() {
    __shared__ __align__(16) float sx[NN];
    __shared__ __align__(16) float sy[NN];
    __shared__ __align__(16) float sz[NN];
    __shared__ float md[256 * 4];
    __shared__ int   mi[256 * 4];
    int b = blockIdx.x >> 5;           // 32 blocks / graph
    int chunk = blockIdx.x & 31;       // 64 queries / block
    int tid = threadIdx.x;
    int gbase = b * NN;
    for (int j = tid; j < NN; j += 256) {
        sx[j] = g_negx[gbase + j];
        sy[j] = g_negy[gbase + j];
        sz[j] = g_negz[gbase + j];
    }
    __syncthreads();
    int ql = tid & 63;
    int sp = tid >> 6;                 // 4 splits x 512 candidates
    int qi = chunk * 64 + ql;
    float qx = -sx[qi], qy = -sy[qi], qz = -sz[qi];
    unsigned long long qx2 = pack2(qx, qx);
    unsigned long long qy2 = pack2(qy, qy);
    unsigned long long qz2 = pack2(qz, qz);
    float b0 = 3.0e38f, b1 = 3.0e38f, b2 = 3.0e38f, b3 = 3.0e38f;
    int i0 = -1, i1 = -1, i2 = -1, i3 = -1;
    int j0 = sp * 512, j1 = j0 + 512;
    bool owns_qi = ((chunk >> 3) == sp);   // uniform per block: is qi inside [j0,j1)?
    if (owns_qi) {
#pragma unroll 4
        for (int j = j0; j < j1; j += 2) {
            unsigned long long px = *(const unsigned long long*)(sx + j);
            unsigned long long py = *(const unsigned long long*)(sy + j);
            unsigned long long pz = *(const unsigned long long*)(sz + j);
            unsigned long long dx = add2(qx2, px);
            unsigned long long dy = add2(qy2, py);
            unsigned long long dz = add2(qz2, pz);
            unsigned long long d2p = add2(add2(mul2(dx, dx), mul2(dy, dy)), mul2(dz, dz));
            float dlo, dhi; unpack2(d2p, dlo, dhi);
            if (dlo < b3 && j != qi)       ins4(dlo, j,     b0, b1, b2, b3, i0, i1, i2, i3);
            if (dhi < b3 && (j + 1) != qi) ins4(dhi, j + 1, b0, b1, b2, b3, i0, i1, i2, i3);
        }
    } else {
#pragma unroll 4
        for (int j = j0; j < j1; j += 2) {
            unsigned long long px = *(const unsigned long long*)(sx + j);
            unsigned long long py = *(const unsigned long long*)(sy + j);
            unsigned long long pz = *(const unsigned long long*)(sz + j);
            unsigned long long dx = add2(qx2, px);
            unsigned long long dy = add2(qy2, py);
            unsigned long long dz = add2(qz2, pz);
            unsigned long long d2p = add2(add2(mul2(dx, dx), mul2(dy, dy)), mul2(dz, dz));
            float dlo, dhi; unpack2(d2p, dlo, dhi);
            if (dlo < b3) ins4(dlo, j,     b0, b1, b2, b3, i0, i1, i2, i3);
            if (dhi < b3) ins4(dhi, j + 1, b0, b1, b2, b3, i0, i1, i2, i3);
        }
    }
    md[tid * 4 + 0] = b0; md[tid * 4 + 1] = b1; md[tid * 4 + 2] = b2; md[tid * 4 + 3] = b3;
    mi[tid * 4 + 0] = i0; mi[tid * 4 + 1] = i1; mi[tid * 4 + 2] = i2; mi[tid * 4 + 3] = i3;
    __syncthreads();
    if (sp == 0) {
        int res[4];
        for (int r = 0; r < 4; r++) {
            float bd = 3.4e38f; int bi = 0x7fffffff; int bloc = -1;
            for (int s2 = 0; s2 < 4; s2++) {
                int base2 = (s2 * 64 + ql) * 4;
#pragma unroll
                for (int k = 0; k < 4; k++) {
                    float d = md[base2 + k]; int ii = mi[base2 + k];
                    if (d < bd || (d == bd && ii < bi)) { bd = d; bi = ii; bloc = base2 + k; }
                }
            }
            md[bloc] = 3.4e38f;
            res[r] = bi;
        }
        int4 o = make_int4(gbase + res[0], gbase + res[1], gbase + res[2], gbase + res[3]);
        *(int4*)&g_knn[(size_t)(gbase + qi) * 4] = o;
    }
}

// ---------------- GCN2: uniform degree 5, norm = 0.2 (2 nodes / block) ----------------
__global__ void k_gcn2(const float* __restrict__ b2) {
    int n = blockIdx.x * 2 + (threadIdx.x >> 7);
    int t = threadIdx.x & 127;
    int4 nb = *(const int4*)&g_knn[(size_t)n * 4];
    float acc = g_xw2[(size_t)n * HIDD + t]
              + g_xw2[(size_t)nb.x * HIDD + t]
              + g_xw2[(size_t)nb.y * HIDD + t]
              + g_xw2[(size_t)nb.z * HIDD + t]
              + g_xw2[(size_t)nb.w * HIDD + t];
    float v = acc * 0.2f + b2[t];
    g_h2[(size_t)n * HIDD + t] = v > 0.f ? v : 0.f;
}

// ---------------- softmax over C=64 (warp per node) + write s slab of dout ----------------
__global__ void k_softmax(const float* __restrict__ bp, float* __restrict__ dout, int limit) {
    int node = (blockIdx.x * 256 + threadIdx.x) >> 5;
    int lane = threadIdx.x & 31;
    float2 l2 = *(const float2*)&g_s[(size_t)node * CC + lane * 2];
    float2 bv = *(const float2*)&bp[lane * 2];
    float a = l2.x + bv.x, c = l2.y + bv.y;
    float mx = fmaxf(a, c);
#pragma unroll
    for (int o = 16; o > 0; o >>= 1) mx = fmaxf(mx, __shfl_xor_sync(0xffffffffu, mx, o));
    float ea = expf(a - mx), ec = expf(c - mx);
    float sum = ea + ec;
#pragma unroll
    for (int o = 16; o > 0; o >>= 1) sum += __shfl_xor_sync(0xffffffffu, sum, o);
    float inv = 1.f / sum;
    ea *= inv; ec *= inv;
    *(float2*)&g_s[(size_t)node * CC + lane * 2] = make_float2(ea, ec);
    int base = 65537 + node * CC + lane * 2;       // odd base -> scalar stores
    if (base + 1 < limit) { dout[base] = ea; dout[base + 1] = ec; }
}

// ---------------- AS[i,:] = sum_{edges src=i} s[colnode,:]  (4 nodes / block) ----------------
__global__ void k_asgather() {
    int n = blockIdx.x * 4 + (threadIdx.x >> 6);
    int t = threadIdx.x & 63;
    int beg = g_off_src[n], end = g_off_src[n + 1];
    float acc = 0.f;
    for (int e = beg; e < end; e++) {
        int j = g_e_by_src[e];
        acc += g_s[(size_t)j * CC + t];
    }
    g_AS[(size_t)n * CC + t] = acc;
}

// ---- fused per-graph: out_adj = S^T AS, ss = S^T S, pool = S^T X, ca/colsum ----
__global__ void k_reduce1() {
    __shared__ float sS[4][64], sA[4][64], sX[4][128], sD[4];
    int b = blockIdx.x >> 4;
    int chunk = blockIdx.x & 15;       // 128 nodes per chunk
    int tid = threadIdx.x;
    int c = tid >> 2, qq = tid & 3;
    int d0 = qq * 16, f0 = qq * 32;
    float aoa[16], ass[16], aout[32];
#pragma unroll
    for (int k = 0; k < 16; k++) { aoa[k] = 0.f; ass[k] = 0.f; }
#pragma unroll
    for (int k = 0; k < 32; k++) aout[k] = 0.f;
    float csum = 0.f, casum = 0.f;
    int node0 = b * NN + chunk * 128;
    for (int nb = 0; nb < 128; nb += 4) {
        {
            int nn2 = tid >> 6, cc2 = tid & 63;
            int node = node0 + nb + nn2;
            sS[nn2][cc2] = g_s[(size_t)node * CC + cc2];
            sA[nn2][cc2] = g_AS[(size_t)node * CC + cc2];
        }
        if (tid < 4) sD[tid] = g_degf[node0 + nb + tid];
        for (int u = tid; u < 4 * 128; u += 256) {
            int nn2 = u >> 7, ff = u & 127;
            int node = node0 + nb + nn2;
            sX[nn2][ff] = g_h2[(size_t)node * HIDD + ff];
        }
        __syncthreads();
#pragma unroll
        for (int nn2 = 0; nn2 < 4; nn2++) {
            float sa = sS[nn2][c];
#pragma unroll
            for (int k = 0; k < 16; k++) {
                aoa[k] += sa * sA[nn2][d0 + k];
                ass[k] += sa * sS[nn2][d0 + k];
            }
#pragma unroll
            for (int k = 0; k < 32; k++) aout[k] += sa * sX[nn2][f0 + k];
            if (qq == 0) { csum += sa; casum += sa * sD[nn2]; }
        }
        __syncthreads();
    }
#pragma unroll
    for (int k = 0; k < 16; k++) {
        atomicAdd(&g_outadj[b * CC * CC + c * CC + d0 + k], aoa[k]);
        atomicAdd(&g_ssm[b * CC * CC + c * CC + d0 + k], ass[k]);
    }
#pragma unroll
    for (int k = 0; k < 32; k++)
        atomicAdd(&g_pool[b * CC * HIDD + c * HIDD + f0 + k], aout[k]);
    if (qq == 0) {
        atomicAdd(&g_colsum[b * CC + c], csum);
        atomicAdd(&g_ca[b * CC + c], casum);
    }
}

// ---------------- losses: one block per graph ----------------
__device__ __forceinline__ float blockReduceSum256(float v, float* sh) {
    sh[threadIdx.x] = v; __syncthreads();
    for (int s = 128; s > 0; s >>= 1) {
        if (threadIdx.x < s) sh[threadIdx.x] += sh[threadIdx.x + s];
        __syncthreads();
    }
    float r = sh[0]; __syncthreads();
    return r;
}

__global__ void k_loss() {
    __shared__ float sh[256];
    int t = threadIdx.x;
    int b = blockIdx.x;
    const float* ss = g_ssm + b * CC * CC;
    const float* oa = g_outadj + b * CC * CC;
    float v = 0.f;
    for (int i = t; i < CC * CC; i += 256) { float w = ss[i]; v += w * w; }
    float fro = sqrtf(blockReduceSum256(v, sh));
    v = 0.f;
    for (int i = t; i < CC * CC; i += 256) {
        float w = ss[i] / fro - ((i % (CC + 1)) == 0 ? 0.125f : 0.f);
        v += w * w;
    }
    float ortho_b = sqrtf(blockReduceSum256(v, sh));
    v = (t < CC) ? oa[t * (CC + 1)] : 0.f;
    float tr = blockReduceSum256(v, sh);
    v = (t < CC) ? g_ca[b * CC + t] * g_ca[b * CC + t] : 0.f;
    float ca2 = blockReduceSum256(v, sh);
    v = (t < CC) ? g_colsum[b * CC + t] * g_colsum[b * CC + t] : 0.f;
    float cs2 = blockReduceSum256(v, sh);
    v = 0.f;
    for (int n = t; n < NN; n += 256) v += g_degf[b * NN + n];
    float twom = blockReduceSum256(v, sh);
    float spectral_b = -(tr - ca2 / twom) / twom;
    float cluster_b = sqrtf(cs2) / (float)NN * 8.0f - 1.0f;
    if (t == 0) g_lossb[b] = spectral_b + ortho_b + cluster_b;
}

// ---------------- selu + log_softmax over F=128 (warp per row) + loss combine ----------------
__global__ void k_selulsm(float* __restrict__ dout, int limit) {
    int row = (blockIdx.x * 256 + threadIdx.x) >> 5;
    int lane = threadIdx.x & 31;
    float4 p = *(const float4*)&g_pool[(size_t)row * HIDD + lane * 4];
    const float SC = 1.0507009873554805f, AL = 1.6732632423543772f;
    float y[4] = {p.x, p.y, p.z, p.w};
#pragma unroll
    for (int k = 0; k < 4; k++) y[k] = y[k] > 0.f ? SC * y[k] : SC * (AL * expm1f(y[k]));
    float mx = fmaxf(fmaxf(y[0], y[1]), fmaxf(y[2], y[3]));
#pragma unroll
    for (int o = 16; o > 0; o >>= 1) mx = fmaxf(mx, __shfl_xor_sync(0xffffffffu, mx, o));
    float sum = 0.f;
#pragma unroll
    for (int k = 0; k < 4; k++) sum += expf(y[k] - mx);
#pragma unroll
    for (int o = 16; o > 0; o >>= 1) sum += __shfl_xor_sync(0xffffffffu, sum, o);
    float lse = logf(sum) + mx;
    int base = row * HIDD + lane * 4;
    if (base + 3 < limit) {
        float4 o4 = make_float4(y[0] - lse, y[1] - lse, y[2] - lse, y[3] - lse);
        *(float4*)&dout[base] = o4;
    }
    if (blockIdx.x == 0 && threadIdx.x == 0 && 65536 < limit) {
        float tot = 0.f;
#pragma unroll
        for (int i = 0; i < BB; i++) tot += g_lossb[i];
        dout[65536] = tot * 0.125f;
    }
}

// ---------------- launcher ----------------
extern "C" void kernel_launch(void* const* d_in, const int* in_sizes, int n_in,
                              void* d_out, int out_size) {
    const float* x    = (const float*)d_in[0];
    const int*   esrc = (const int*)d_in[1];
    const int*   edst = (const int*)d_in[2];
    // d_in[3] = batch (unused)
    const float* W1 = (const float*)d_in[4];
    const float* b1 = (const float*)d_in[5];
    const float* W2 = (const float*)d_in[6];
    const float* b2 = (const float*)d_in[7];
    const float* Wp = (const float*)d_in[8];
    const float* bp = (const float*)d_in[9];
    float* out = (float*)d_out;

    k_init<<<256, 256>>>();
    k_count<<<EE / 256, 256>>>(esrc, edst);
    k_scan<<<3, 1024>>>();
    k_fill<<<EE / 256, 256>>>(esrc, edst);
    k_sort<<<BN / 128, 128>>>();
    k_gemm1<<<dim3(2, 256), 256>>>(x, W1);
    k_gcn1<<<BN, 128>>>(b1);
    k_knn<<<256, 256>>>();
    k_gemm2<<<dim3(2, 256), 256>>>(W2);
    k_gcn2<<<BN / 2, 256>>>(b2);
    k_gemm3<<<dim3(1, 256), 256>>>(Wp);
    k_softmax<<<BN / 8, 256>>>(bp, out, out_size);
    k_asgather<<<BN / 4, 256>>>();
    k_reduce1<<<128, 256>>>();
    k_loss<<<BB, 256>>>();
    k_selulsm<<<BB * CC / 8, 256>>>(out, out_size);
}

// round 10
// speedup vs baseline: 2.4382x; 1.4450x over previous
#include <cuda_runtime.h>
#include <math.h>

#define BB 8
#define NN 2048
#define BN 16384
#define INCH 16
#define HIDD 128
#define CC 64
#define EE 262144

// ---------------- scratch ----------------
__device__ float g_ax[BN * INCH];
__device__ float g_h1[BN * HIDD];
__device__ float g_xw2[BN * HIDD];
__device__ float g_h2[BN * HIDD];
__device__ float g_s[BN * CC];
__device__ float g_AS[BN * CC];
__device__ float g_dis[BN];
__device__ float g_degf[BN];
__device__ float g_negx[BN];
__device__ float g_negy[BN];
__device__ float g_negz[BN];
__device__ int   g_cnt_dst[BN];
__device__ int   g_cnt_src[BN];
__device__ int   g_cnt_d2[BN];
__device__ int   g_cur_dst[BN];
__device__ int   g_cur_src[BN];
__device__ int   g_off_dst[BN + 1];
__device__ int   g_off_src[BN + 1];
__device__ int   g_e_by_dst[EE];
__device__ int   g_e_by_src[EE];
__device__ int   g_knn[BN * 4];
__device__ float g_ssm[BB * CC * CC];
__device__ float g_pool[BB * CC * HIDD];
__device__ float g_ca[BB * CC];
__device__ float g_colsum[BB * CC];
__device__ float g_tr[BB];
__device__ float g_lossb[BB];

// ---------------- packed f32x2 helpers (lane-wise IEEE rn, same rounding as scalar) ----
__device__ __forceinline__ unsigned long long pack2(float a, float b) {
    unsigned long long r;
    asm("mov.b64 %0, {%1, %2};" : "=l"(r) : "f"(a), "f"(b));
    return r;
}
__device__ __forceinline__ void unpack2(unsigned long long v, float& lo, float& hi) {
    asm("mov.b64 {%0, %1}, %2;" : "=f"(lo), "=f"(hi) : "l"(v));
}
__device__ __forceinline__ unsigned long long add2(unsigned long long a, unsigned long long b) {
    unsigned long long r;
    asm("add.rn.f32x2 %0, %1, %2;" : "=l"(r) : "l"(a), "l"(b));
    return r;
}
__device__ __forceinline__ unsigned long long mul2(unsigned long long a, unsigned long long b) {
    unsigned long long r;
    asm("mul.rn.f32x2 %0, %1, %2;" : "=l"(r) : "l"(a), "l"(b));
    return r;
}

// ---------------- init ----------------
__global__ void k_init() {
    int i = blockIdx.x * blockDim.x + threadIdx.x;
    int st = gridDim.x * blockDim.x;
    for (int k = i; k < BN; k += st) {
        g_cnt_dst[k] = 0; g_cnt_src[k] = 0; g_cnt_d2[k] = 0;
        g_cur_dst[k] = 0; g_cur_src[k] = 0;
    }
    for (int k = i; k < BB * CC * CC; k += st) g_ssm[k] = 0.f;
    for (int k = i; k < BB * CC * HIDD; k += st) g_pool[k] = 0.f;
    for (int k = i; k < BB * CC; k += st) { g_ca[k] = 0.f; g_colsum[k] = 0.f; }
    if (i < BB) g_tr[i] = 0.f;
}

// ---------------- edge counting ----------------
__global__ void k_count(const int* __restrict__ esrc, const int* __restrict__ edst) {
    int e = blockIdx.x * blockDim.x + threadIdx.x;
    if (e >= EE) return;
    int s = esrc[e], d = edst[e];
    atomicAdd(&g_cnt_dst[d], 1);
    atomicAdd(&g_cnt_src[s], 1);
    int d2 = (s / NN) * NN + (d % NN);     // DMoN adj column node
    atomicAdd(&g_cnt_d2[d2], 1);
}

// blocks 0/1: exclusive scans (dst CSR, src CSR).  block 2: nodeprep.
__global__ void k_scan() {
    if (blockIdx.x == 2) {
        int t = threadIdx.x;
        for (int n = t; n < BN; n += 1024) {
            g_dis[n] = rsqrtf((float)(g_cnt_dst[n] + 1));
            g_degf[n] = (float)g_cnt_d2[n];
        }
        return;
    }
    __shared__ int part[1024];
    const int* cnt = (blockIdx.x == 0) ? g_cnt_dst : g_cnt_src;
    int* off = (blockIdx.x == 0) ? g_off_dst : g_off_src;
    int t = threadIdx.x;
    int base = t * 16;
    int loc[16]; int s = 0;
#pragma unroll
    for (int i = 0; i < 16; i++) { loc[i] = s; s += cnt[base + i]; }
    part[t] = s; __syncthreads();
    for (int d = 1; d < 1024; d <<= 1) {
        int v = (t >= d) ? part[t - d] : 0;
        __syncthreads();
        part[t] += v;
        __syncthreads();
    }
    int pre = t ? part[t - 1] : 0;
#pragma unroll
    for (int i = 0; i < 16; i++) off[base + i] = pre + loc[i];
    if (t == 1023) off[BN] = part[1023];
}

__global__ void k_fill(const int* __restrict__ esrc, const int* __restrict__ edst) {
    int e = blockIdx.x * blockDim.x + threadIdx.x;
    if (e >= EE) return;
    int s = esrc[e], d = edst[e];
    int p = g_off_dst[d] + atomicAdd(&g_cur_dst[d], 1);
    g_e_by_dst[p] = s;
    int d2 = (s / NN) * NN + (d % NN);
    int q = g_off_src[s] + atomicAdd(&g_cur_src[s], 1);
    g_e_by_src[q] = d2;
}

// ---------------- aggregate-then-transform: g_ax = Ahat @ X  (16 ch) ----------------
__global__ void k_aggx(const float* __restrict__ x) {
    int node = blockIdx.x * 16 + (threadIdx.x >> 4);
    int t = threadIdx.x & 15;
    int beg = g_off_dst[node], end = g_off_dst[node + 1];
    float dn = g_dis[node];
    float acc = x[node * INCH + t] * (dn * dn);
    for (int e = beg; e < end; e++) {
        int s = g_e_by_dst[e];
        acc += x[s * INCH + t] * (g_dis[s] * dn);
    }
    g_ax[node * INCH + t] = acc;
}

// ---------------- GEMM1 fused: h1 = relu(g_ax @ W1 + b1), coords extracted ----------------
__global__ void k_gemm1f(const float* __restrict__ W1, const float* __restrict__ b1) {
    __shared__ float As[16][64];
    __shared__ float Bs[16][64];
    int tid = threadIdx.x;
    int bx = blockIdx.x, by = blockIdx.y;
    int tx = tid & 15, ty = tid >> 4;
    float acc[4][4];
#pragma unroll
    for (int i = 0; i < 4; i++)
#pragma unroll
        for (int j = 0; j < 4; j++) acc[i][j] = 0.f;
    int arow = tid >> 2, acol = (tid & 3) << 2;
    int brow = tid >> 4, bcol = (tid & 15) << 2;
    {
        float4 av = *(const float4*)(g_ax + (size_t)(by * 64 + arow) * INCH + acol);
        float4 bv = *(const float4*)(W1 + (size_t)brow * HIDD + bx * 64 + bcol);
        As[acol + 0][arow] = av.x; As[acol + 1][arow] = av.y;
        As[acol + 2][arow] = av.z; As[acol + 3][arow] = av.w;
        *(float4*)&Bs[brow][bcol] = bv;
        __syncthreads();
#pragma unroll
        for (int kk = 0; kk < 16; kk++) {
            float4 a = *(const float4*)&As[kk][ty << 2];
            float4 b = *(const float4*)&Bs[kk][tx << 2];
            float aa[4] = {a.x, a.y, a.z, a.w};
            float bb[4] = {b.x, b.y, b.z, b.w};
#pragma unroll
            for (int i = 0; i < 4; i++)
#pragma unroll
                for (int j = 0; j < 4; j++) acc[i][j] += aa[i] * bb[j];
        }
    }
    int col0 = bx * 64 + (tx << 2);
    float4 bv = *(const float4*)&b1[col0];
    float bb[4] = {bv.x, bv.y, bv.z, bv.w};
#pragma unroll
    for (int i = 0; i < 4; i++) {
        int row = by * 64 + (ty << 2) + i;
        float r[4];
#pragma unroll
        for (int j = 0; j < 4; j++) {
            float v = acc[i][j] + bb[j];
            r[j] = v > 0.f ? v : 0.f;
        }
        *(float4*)(g_h1 + (size_t)row * HIDD + col0) = make_float4(r[0], r[1], r[2], r[3]);
        if (bx == 0 && tx == 0) {
            g_negx[row] = -r[0];
            g_negy[row] = -r[1];
            g_negz[row] = -r[2];
        }
    }
}

// ---------------- KNN brute force, k=4, packed f32x2, lowest-index tie-break ----------------
__device__ __forceinline__ void ins4(float d2, int j,
                                     float& b0, float& b1, float& b2, float& b3,
                                     int& i0, int& i1, int& i2, int& i3) {
    if (d2 < b1) {
        b3 = b2; i3 = i2; b2 = b1; i2 = i1;
        if (d2 < b0) { b1 = b0; i1 = i0; b0 = d2; i0 = j; }
        else { b1 = d2; i1 = j; }
    } else {
        if (d2 < b2) { b3 = b2; i3 = i2; b2 = d2; i2 = j; }
        else { b3 = d2; i3 = j; }
    }
}

__global__ void k_knn() {
    __shared__ __align__(16) float sx[NN];
    __shared__ __align__(16) float sy[NN];
    __shared__ __align__(16) float sz[NN];
    __shared__ float md[256 * 4];
    __shared__ int   mi[256 * 4];
    int b = blockIdx.x >> 5;           // 32 blocks / graph
    int chunk = blockIdx.x & 31;       // 64 queries / block
    int tid = threadIdx.x;
    int gbase = b * NN;
    for (int j = tid; j < NN; j += 256) {
        sx[j] = g_negx[gbase + j];
        sy[j] = g_negy[gbase + j];
        sz[j] = g_negz[gbase + j];
    }
    __syncthreads();
    int ql = tid & 63;
    int sp = tid >> 6;                 // 4 splits x 512 candidates
    int qi = chunk * 64 + ql;
    float qx = -sx[qi], qy = -sy[qi], qz = -sz[qi];
    unsigned long long qx2 = pack2(qx, qx);
    unsigned long long qy2 = pack2(qy, qy);
    unsigned long long qz2 = pack2(qz, qz);
    float b0 = 3.0e38f, b1 = 3.0e38f, b2 = 3.0e38f, b3 = 3.0e38f;
    int i0 = -1, i1 = -1, i2 = -1, i3 = -1;
    int j0 = sp * 512, j1 = j0 + 512;
    bool owns_qi = ((chunk >> 3) == sp);
    if (owns_qi) {
#pragma unroll 4
        for (int j = j0; j < j1; j += 2) {
            unsigned long long px = *(const unsigned long long*)(sx + j);
            unsigned long long py = *(const unsigned long long*)(sy + j);
            unsigned long long pz = *(const unsigned long long*)(sz + j);
            unsigned long long dx = add2(qx2, px);
            unsigned long long dy = add2(qy2, py);
            unsigned long long dz = add2(qz2, pz);
            unsigned long long d2p = add2(add2(mul2(dx, dx), mul2(dy, dy)), mul2(dz, dz));
            float dlo, dhi; unpack2(d2p, dlo, dhi);
            if (dlo < b3 && j != qi)       ins4(dlo, j,     b0, b1, b2, b3, i0, i1, i2, i3);
            if (dhi < b3 && (j + 1) != qi) ins4(dhi, j + 1, b0, b1, b2, b3, i0, i1, i2, i3);
        }
    } else {
#pragma unroll 4
        for (int j = j0; j < j1; j += 2) {
            unsigned long long px = *(const unsigned long long*)(sx + j);
            unsigned long long py = *(const unsigned long long*)(sy + j);
            unsigned long long pz = *(const unsigned long long*)(sz + j);
            unsigned long long dx = add2(qx2, px);
            unsigned long long dy = add2(qy2, py);
            unsigned long long dz = add2(qz2, pz);
            unsigned long long d2p = add2(add2(mul2(dx, dx), mul2(dy, dy)), mul2(dz, dz));
            float dlo, dhi; unpack2(d2p, dlo, dhi);
            if (dlo < b3) ins4(dlo, j,     b0, b1, b2, b3, i0, i1, i2, i3);
            if (dhi < b3) ins4(dhi, j + 1, b0, b1, b2, b3, i0, i1, i2, i3);
        }
    }
    md[tid * 4 + 0] = b0; md[tid * 4 + 1] = b1; md[tid * 4 + 2] = b2; md[tid * 4 + 3] = b3;
    mi[tid * 4 + 0] = i0; mi[tid * 4 + 1] = i1; mi[tid * 4 + 2] = i2; mi[tid * 4 + 3] = i3;
    __syncthreads();
    if (sp == 0) {
        int res[4];
        for (int r = 0; r < 4; r++) {
            float bd = 3.4e38f; int bi = 0x7fffffff; int bloc = -1;
            for (int s2 = 0; s2 < 4; s2++) {
                int base2 = (s2 * 64 + ql) * 4;
#pragma unroll
                for (int k = 0; k < 4; k++) {
                    float d = md[base2 + k]; int ii = mi[base2 + k];
                    if (d < bd || (d == bd && ii < bi)) { bd = d; bi = ii; bloc = base2 + k; }
                }
            }
            md[bloc] = 3.4e38f;
            res[r] = bi;
        }
        int4 o = make_int4(gbase + res[0], gbase + res[1], gbase + res[2], gbase + res[3]);
        *(int4*)&g_knn[(size_t)(gbase + qi) * 4] = o;
    }
}

// ---------------- tiled GEMM2: g_xw2 = h1 @ W2 ----------------
__global__ void k_gemm2(const float* __restrict__ W2) {
    __shared__ float As[16][64];
    __shared__ float Bs[16][64];
    int tid = threadIdx.x;
    int bx = blockIdx.x, by = blockIdx.y;
    int tx = tid & 15, ty = tid >> 4;
    float acc[4][4];
#pragma unroll
    for (int i = 0; i < 4; i++)
#pragma unroll
        for (int j = 0; j < 4; j++) acc[i][j] = 0.f;
    int arow = tid >> 2, acol = (tid & 3) << 2;
    int brow = tid >> 4, bcol = (tid & 15) << 2;
    const float* Ap = g_h1 + (size_t)(by * 64 + arow) * HIDD + acol;
    const float* Wq = W2 + (size_t)brow * HIDD + bx * 64 + bcol;
    for (int kt = 0; kt < HIDD; kt += 16) {
        float4 av = *(const float4*)(Ap + kt);
        float4 bv = *(const float4*)(Wq + (size_t)kt * HIDD);
        As[acol + 0][arow] = av.x; As[acol + 1][arow] = av.y;
        As[acol + 2][arow] = av.z; As[acol + 3][arow] = av.w;
        *(float4*)&Bs[brow][bcol] = bv;
        __syncthreads();
#pragma unroll
        for (int kk = 0; kk < 16; kk++) {
            float4 a = *(const float4*)&As[kk][ty << 2];
            float4 b = *(const float4*)&Bs[kk][tx << 2];
            float aa[4] = {a.x, a.y, a.z, a.w};
            float bb[4] = {b.x, b.y, b.z, b.w};
#pragma unroll
            for (int i = 0; i < 4; i++)
#pragma unroll
                for (int j = 0; j < 4; j++) acc[i][j] += aa[i] * bb[j];
        }
        __syncthreads();
    }
#pragma unroll
    for (int i = 0; i < 4; i++) {
        float4 v = make_float4(acc[i][0], acc[i][1], acc[i][2], acc[i][3]);
        *(float4*)(g_xw2 + (size_t)(by * 64 + (ty << 2) + i) * HIDD + bx * 64 + (tx << 2)) = v;
    }
}

// ---------------- GCN2: uniform degree 5, norm = 0.2 (2 nodes / block) ----------------
__global__ void k_gcn2(const float* __restrict__ b2) {
    int n = blockIdx.x * 2 + (threadIdx.x >> 7);
    int t = threadIdx.x & 127;
    int4 nb = *(const int4*)&g_knn[(size_t)n * 4];
    float acc = g_xw2[(size_t)n * HIDD + t]
              + g_xw2[(size_t)nb.x * HIDD + t]
              + g_xw2[(size_t)nb.y * HIDD + t]
              + g_xw2[(size_t)nb.z * HIDD + t]
              + g_xw2[(size_t)nb.w * HIDD + t];
    float v = acc * 0.2f + b2[t];
    g_h2[(size_t)n * HIDD + t] = v > 0.f ? v : 0.f;
}

// ---------------- GEMM3 fused: s = softmax(h2 @ Wp + bp), writes g_s + dout slab ----------------
__global__ void k_gemm3s(const float* __restrict__ Wp, const float* __restrict__ bp,
                         float* __restrict__ dout, int limit) {
    __shared__ float As[16][64];
    __shared__ float Bs[16][64];
    int tid = threadIdx.x;
    int by = blockIdx.x;
    int tx = tid & 15, ty = tid >> 4;
    float acc[4][4];
#pragma unroll
    for (int i = 0; i < 4; i++)
#pragma unroll
        for (int j = 0; j < 4; j++) acc[i][j] = 0.f;
    int arow = tid >> 2, acol = (tid & 3) << 2;
    int brow = tid >> 4, bcol = (tid & 15) << 2;
    const float* Ap = g_h2 + (size_t)(by * 64 + arow) * HIDD + acol;
    const float* Wq = Wp + (size_t)brow * CC + bcol;
    for (int kt = 0; kt < HIDD; kt += 16) {
        float4 av = *(const float4*)(Ap + kt);
        float4 bv = *(const float4*)(Wq + (size_t)kt * CC);
        As[acol + 0][arow] = av.x; As[acol + 1][arow] = av.y;
        As[acol + 2][arow] = av.z; As[acol + 3][arow] = av.w;
        *(float4*)&Bs[brow][bcol] = bv;
        __syncthreads();
#pragma unroll
        for (int kk = 0; kk < 16; kk++) {
            float4 a = *(const float4*)&As[kk][ty << 2];
            float4 b = *(const float4*)&Bs[kk][tx << 2];
            float aa[4] = {a.x, a.y, a.z, a.w};
            float bb[4] = {b.x, b.y, b.z, b.w};
#pragma unroll
            for (int i = 0; i < 4; i++)
#pragma unroll
                for (int j = 0; j < 4; j++) acc[i][j] += aa[i] * bb[j];
        }
        __syncthreads();
    }
    // epilogue: bias + row softmax (row owned by 16 lanes of same ty -> shfl in 16-lane group)
    float4 bv = *(const float4*)&bp[tx << 2];
    float bb[4] = {bv.x, bv.y, bv.z, bv.w};
#pragma unroll
    for (int i = 0; i < 4; i++) {
        float v[4];
#pragma unroll
        for (int j = 0; j < 4; j++) v[j] = acc[i][j] + bb[j];
        float m = fmaxf(fmaxf(v[0], v[1]), fmaxf(v[2], v[3]));
#pragma unroll
        for (int o = 8; o > 0; o >>= 1) m = fmaxf(m, __shfl_xor_sync(0xffffffffu, m, o));
        float e[4]; float sum = 0.f;
#pragma unroll
        for (int j = 0; j < 4; j++) { e[j] = expf(v[j] - m); sum += e[j]; }
#pragma unroll
        for (int o = 8; o > 0; o >>= 1) sum += __shfl_xor_sync(0xffffffffu, sum, o);
        float inv = 1.f / sum;
#pragma unroll
        for (int j = 0; j < 4; j++) e[j] *= inv;
        int row = by * 64 + (ty << 2) + i;
        *(float4*)(g_s + (size_t)row * CC + (tx << 2)) = make_float4(e[0], e[1], e[2], e[3]);
        int base = 65537 + row * CC + (tx << 2);
#pragma unroll
        for (int j = 0; j < 4; j++)
            if (base + j < limit) dout[base + j] = e[j];
    }
}

// ---- AS[i,:] = sum_{edges src=i} s[colnode,:] ; also trace(S^T A S) accumulation ----
__global__ void k_asgather() {
    __shared__ float str;
    int n = blockIdx.x * 4 + (threadIdx.x >> 6);
    int t = threadIdx.x & 63;
    if (threadIdx.x == 0) str = 0.f;
    __syncthreads();
    int beg = g_off_src[n], end = g_off_src[n + 1];
    float acc = 0.f;
    for (int e = beg; e < end; e++) {
        int j = g_e_by_src[e];
        acc += g_s[(size_t)j * CC + t];
    }
    g_AS[(size_t)n * CC + t] = acc;
    float c = acc * g_s[(size_t)n * CC + t];
#pragma unroll
    for (int o = 16; o > 0; o >>= 1) c += __shfl_xor_sync(0xffffffffu, c, o);
    if ((threadIdx.x & 31) == 0) atomicAdd(&str, c);
    __syncthreads();
    if (threadIdx.x == 0) atomicAdd(&g_tr[blockIdx.x >> 9], str);
}

// ---- fused per-graph: ss = S^T S, pool = S^T X, ca/colsum ----
__global__ void k_reduce1() {
    __shared__ float sS[4][64], sX[4][128], sD[4];
    int b = blockIdx.x >> 4;
    int chunk = blockIdx.x & 15;       // 128 nodes per chunk
    int tid = threadIdx.x;
    int c = tid >> 2, qq = tid & 3;
    int d0 = qq * 16, f0 = qq * 32;
    float ass[16], aout[32];
#pragma unroll
    for (int k = 0; k < 16; k++) ass[k] = 0.f;
#pragma unroll
    for (int k = 0; k < 32; k++) aout[k] = 0.f;
    float csum = 0.f, casum = 0.f;
    int node0 = b * NN + chunk * 128;
    for (int nb = 0; nb < 128; nb += 4) {
        {
            int nn2 = tid >> 6, cc2 = tid & 63;
            int node = node0 + nb + nn2;
            sS[nn2][cc2] = g_s[(size_t)node * CC + cc2];
        }
        if (tid < 4) sD[tid] = g_degf[node0 + nb + tid];
        for (int u = tid; u < 4 * 128; u += 256) {
            int nn2 = u >> 7, ff = u & 127;
            int node = node0 + nb + nn2;
            sX[nn2][ff] = g_h2[(size_t)node * HIDD + ff];
        }
        __syncthreads();
#pragma unroll
        for (int nn2 = 0; nn2 < 4; nn2++) {
            float sa = sS[nn2][c];
#pragma unroll
            for (int k = 0; k < 16; k++) ass[k] += sa * sS[nn2][d0 + k];
#pragma unroll
            for (int k = 0; k < 32; k++) aout[k] += sa * sX[nn2][f0 + k];
            if (qq == 0) { csum += sa; casum += sa * sD[nn2]; }
        }
        __syncthreads();
    }
#pragma unroll
    for (int k = 0; k < 16; k++)
        atomicAdd(&g_ssm[b * CC * CC + c * CC + d0 + k], ass[k]);
#pragma unroll
    for (int k = 0; k < 32; k++)
        atomicAdd(&g_pool[b * CC * HIDD + c * HIDD + f0 + k], aout[k]);
    if (qq == 0) {
        atomicAdd(&g_colsum[b * CC + c], csum);
        atomicAdd(&g_ca[b * CC + c], casum);
    }
}

// ---------------- losses: one block per graph ----------------
__device__ __forceinline__ float blockReduceSum256(float v, float* sh) {
    sh[threadIdx.x] = v; __syncthreads();
    for (int s = 128; s > 0; s >>= 1) {
        if (threadIdx.x < s) sh[threadIdx.x] += sh[threadIdx.x + s];
        __syncthreads();
    }
    float r = sh[0]; __syncthreads();
    return r;
}

__global__ void k_loss() {
    __shared__ float sh[256];
    int t = threadIdx.x;
    int b = blockIdx.x;
    const float* ss = g_ssm + b * CC * CC;
    float v = 0.f;
    for (int i = t; i < CC * CC; i += 256) { float w = ss[i]; v += w * w; }
    float fro = sqrtf(blockReduceSum256(v, sh));
    v = 0.f;
    for (int i = t; i < CC * CC; i += 256) {
        float w = ss[i] / fro - ((i % (CC + 1)) == 0 ? 0.125f : 0.f);
        v += w * w;
    }
    float ortho_b = sqrtf(blockReduceSum256(v, sh));
    v = (t < CC) ? g_ca[b * CC + t] * g_ca[b * CC + t] : 0.f;
    float ca2 = blockReduceSum256(v, sh);
    v = (t < CC) ? g_colsum[b * CC + t] * g_colsum[b * CC + t] : 0.f;
    float cs2 = blockReduceSum256(v, sh);
    v = 0.f;
    for (int n = t; n < NN; n += 256) v += g_degf[b * NN + n];
    float twom = blockReduceSum256(v, sh);
    float tr = g_tr[b];
    float spectral_b = -(tr - ca2 / twom) / twom;
    float cluster_b = sqrtf(cs2) / (float)NN * 8.0f - 1.0f;
    if (t == 0) g_lossb[b] = spectral_b + ortho_b + cluster_b;
}

// ---------------- selu + log_softmax over F=128 (warp per row) + loss combine ----------------
__global__ void k_selulsm(float* __restrict__ dout, int limit) {
    int row = (blockIdx.x * 256 + threadIdx.x) >> 5;
    int lane = threadIdx.x & 31;
    float4 p = *(const float4*)&g_pool[(size_t)row * HIDD + lane * 4];
    const float SC = 1.0507009873554805f, AL = 1.6732632423543772f;
    float y[4] = {p.x, p.y, p.z, p.w};
#pragma unroll
    for (int k = 0; k < 4; k++) y[k] = y[k] > 0.f ? SC * y[k] : SC * (AL * expm1f(y[k]));
    float mx = fmaxf(fmaxf(y[0], y[1]), fmaxf(y[2], y[3]));
#pragma unroll
    for (int o = 16; o > 0; o >>= 1) mx = fmaxf(mx, __shfl_xor_sync(0xffffffffu, mx, o));
    float sum = 0.f;
#pragma unroll
    for (int k = 0; k < 4; k++) sum += expf(y[k] - mx);
#pragma unroll
    for (int o = 16; o > 0; o >>= 1) sum += __shfl_xor_sync(0xffffffffu, sum, o);
    float lse = logf(sum) + mx;
    int base = row * HIDD + lane * 4;
    if (base + 3 < limit) {
        float4 o4 = make_float4(y[0] - lse, y[1] - lse, y[2] - lse, y[3] - lse);
        *(float4*)&dout[base] = o4;
    }
    if (blockIdx.x == 0 && threadIdx.x == 0 && 65536 < limit) {
        float tot = 0.f;
#pragma unroll
        for (int i = 0; i < BB; i++) tot += g_lossb[i];
        dout[65536] = tot * 0.125f;
    }
}

// ---------------- launcher ----------------
extern "C" void kernel_launch(void* const* d_in, const int* in_sizes, int n_in,
                              void* d_out, int out_size) {
    const float* x    = (const float*)d_in[0];
    const int*   esrc = (const int*)d_in[1];
    const int*   edst = (const int*)d_in[2];
    // d_in[3] = batch (unused)
    const float* W1 = (const float*)d_in[4];
    const float* b1 = (const float*)d_in[5];
    const float* W2 = (const float*)d_in[6];
    const float* b2 = (const float*)d_in[7];
    const float* Wp = (const float*)d_in[8];
    const float* bp = (const float*)d_in[9];
    float* out = (float*)d_out;

    k_init<<<256, 256>>>();
    k_count<<<EE / 256, 256>>>(esrc, edst);
    k_scan<<<3, 1024>>>();
    k_fill<<<EE / 256, 256>>>(esrc, edst);
    k_aggx<<<BN / 16, 256>>>(x);
    k_gemm1f<<<dim3(2, 256), 256>>>(W1, b1);
    k_knn<<<256, 256>>>();
    k_gemm2<<<dim3(2, 256), 256>>>(W2);
    k_gcn2<<<BN / 2, 256>>>(b2);
    k_gemm3s<<<256, 256>>>(Wp, bp, out, out_size);
    k_asgather<<<BN / 4, 256>>>();
    k_reduce1<<<128, 256>>>();
    k_loss<<<BB, 256>>>();
    k_selulsm<<<BB * CC / 8, 256>>>(out, out_size);
}

// round 11
// speedup vs baseline: 2.6579x; 1.0901x over previous
#include <cuda_runtime.h>
#include <math.h>

#define BB 8
#define NN 2048
#define BN 16384
#define INCH 16
#define HIDD 128
#define CC 64
#define EE 262144

// ---------------- scratch ----------------
__device__ float g_ax[BN * INCH];
__device__ float g_h1[BN * HIDD];
__device__ float g_xw2[BN * HIDD];
__device__ float g_h2[BN * HIDD];
__device__ float g_s[BN * CC];
__device__ float g_AS[BN * CC];
__device__ float g_dis[BN];
__device__ float g_degf[BN];
__device__ float g_negx[BN];
__device__ float g_negy[BN];
__device__ float g_negz[BN];
__device__ int   g_cnt_dst[BN];
__device__ int   g_cnt_src[BN];
__device__ int   g_cnt_d2[BN];
__device__ int   g_cur_dst[BN];
__device__ int   g_cur_src[BN];
__device__ int   g_off_dst[BN + 1];
__device__ int   g_off_src[BN + 1];
__device__ int   g_e_by_dst[EE];
__device__ int   g_e_by_src[EE];
__device__ int   g_knn[BN * 4];
__device__ float g_ssm[BB * CC * CC];
__device__ float g_pool[BB * CC * HIDD];
__device__ float g_ca[BB * CC];
__device__ float g_colsum[BB * CC];
__device__ float g_tr[BB];
__device__ float g_lossb[BB];

// ---------------- packed f32x2 helpers ----------------
__device__ __forceinline__ unsigned long long pack2(float a, float b) {
    unsigned long long r;
    asm("mov.b64 %0, {%1, %2};" : "=l"(r) : "f"(a), "f"(b));
    return r;
}
__device__ __forceinline__ void unpack2(unsigned long long v, float& lo, float& hi) {
    asm("mov.b64 {%0, %1}, %2;" : "=f"(lo), "=f"(hi) : "l"(v));
}
__device__ __forceinline__ unsigned long long add2(unsigned long long a, unsigned long long b) {
    unsigned long long r;
    asm("add.rn.f32x2 %0, %1, %2;" : "=l"(r) : "l"(a), "l"(b));
    return r;
}
__device__ __forceinline__ unsigned long long mul2(unsigned long long a, unsigned long long b) {
    unsigned long long r;
    asm("mul.rn.f32x2 %0, %1, %2;" : "=l"(r) : "l"(a), "l"(b));
    return r;
}

// ---------------- init ----------------
__global__ void k_init() {
    int i = blockIdx.x * blockDim.x + threadIdx.x;
    int st = gridDim.x * blockDim.x;
    for (int k = i; k < BN; k += st) {
        g_cnt_dst[k] = 0; g_cnt_src[k] = 0; g_cnt_d2[k] = 0;
        g_cur_dst[k] = 0; g_cur_src[k] = 0;
    }
    for (int k = i; k < BB * CC * CC; k += st) g_ssm[k] = 0.f;
    for (int k = i; k < BB * CC * HIDD; k += st) g_pool[k] = 0.f;
    for (int k = i; k < BB * CC; k += st) { g_ca[k] = 0.f; g_colsum[k] = 0.f; }
    if (i < BB) g_tr[i] = 0.f;
}

// ---------------- edge counting, split by consumer lane ----------------
__global__ void k_count_dst(const int* __restrict__ esrc, const int* __restrict__ edst) {
    int e = blockIdx.x * blockDim.x + threadIdx.x;
    if (e >= EE) return;
    int s = esrc[e], d = edst[e];
    atomicAdd(&g_cnt_dst[d], 1);
    int d2 = (s / NN) * NN + (d % NN);
    atomicAdd(&g_cnt_d2[d2], 1);
}
__global__ void k_count_src(const int* __restrict__ esrc) {
    int e = blockIdx.x * blockDim.x + threadIdx.x;
    if (e >= EE) return;
    atomicAdd(&g_cnt_src[esrc[e]], 1);
}

// exclusive scan of 16384 ints (1024 threads, 16 per thread)
__device__ __forceinline__ void scan_body(const int* cnt, int* off) {
    __shared__ int part[1024];
    int t = threadIdx.x;
    int base = t * 16;
    int loc[16]; int s = 0;
#pragma unroll
    for (int i = 0; i < 16; i++) { loc[i] = s; s += cnt[base + i]; }
    part[t] = s; __syncthreads();
    for (int d = 1; d < 1024; d <<= 1) {
        int v = (t >= d) ? part[t - d] : 0;
        __syncthreads();
        part[t] += v;
        __syncthreads();
    }
    int pre = t ? part[t - 1] : 0;
#pragma unroll
    for (int i = 0; i < 16; i++) off[base + i] = pre + loc[i];
    if (t == 1023) off[16384] = part[1023];
}

// block 0: dst scan, block 1: nodeprep
__global__ void k_scan_dst() {
    if (blockIdx.x == 1) {
        int t = threadIdx.x;
        for (int n = t; n < BN; n += 1024) {
            g_dis[n] = rsqrtf((float)(g_cnt_dst[n] + 1));
            g_degf[n] = (float)g_cnt_d2[n];
        }
        return;
    }
    scan_body(g_cnt_dst, g_off_dst);
}
__global__ void k_scan_src() { scan_body(g_cnt_src, g_off_src); }

__global__ void k_fill_dst(const int* __restrict__ esrc, const int* __restrict__ edst) {
    int e = blockIdx.x * blockDim.x + threadIdx.x;
    if (e >= EE) return;
    int s = esrc[e], d = edst[e];
    int p = g_off_dst[d] + atomicAdd(&g_cur_dst[d], 1);
    g_e_by_dst[p] = s;
}
__global__ void k_fill_src(const int* __restrict__ esrc, const int* __restrict__ edst) {
    int e = blockIdx.x * blockDim.x + threadIdx.x;
    if (e >= EE) return;
    int s = esrc[e], d = edst[e];
    int d2 = (s / NN) * NN + (d % NN);
    int q = g_off_src[s] + atomicAdd(&g_cur_src[s], 1);
    g_e_by_src[q] = d2;
}

// ---------------- aggregate-then-transform: g_ax = Ahat @ X  (16 ch) ----------------
__global__ void k_aggx(const float* __restrict__ x) {
    int node = blockIdx.x * 16 + (threadIdx.x >> 4);
    int t = threadIdx.x & 15;
    int beg = g_off_dst[node], end = g_off_dst[node + 1];
    float dn = g_dis[node];
    float acc = x[node * INCH + t] * (dn * dn);
    for (int e = beg; e < end; e++) {
        int s = g_e_by_dst[e];
        acc += x[s * INCH + t] * (g_dis[s] * dn);
    }
    g_ax[node * INCH + t] = acc;
}

// ---------------- coords only: h1[:,0:3] bitwise-identical to gemm1f, negated ----------------
__global__ void k_coord3(const float* __restrict__ W1, const float* __restrict__ b1) {
    __shared__ float sW[48];   // [k][j] = W1[k*HIDD + j], k<16, j<3
    __shared__ float sB[3];
    int t = threadIdx.x;
    if (t < 48) sW[t] = W1[(t / 3) * HIDD + (t % 3)];
    if (t < 3) sB[t] = b1[t];
    __syncthreads();
    int n = blockIdx.x * 256 + t;
    const float4* ap = (const float4*)(g_ax + (size_t)n * INCH);
    float4 a0 = ap[0], a1 = ap[1], a2 = ap[2], a3 = ap[3];
    float a[16] = {a0.x, a0.y, a0.z, a0.w, a1.x, a1.y, a1.z, a1.w,
                   a2.x, a2.y, a2.z, a2.w, a3.x, a3.y, a3.z, a3.w};
    float acc0 = 0.f, acc1 = 0.f, acc2 = 0.f;
#pragma unroll
    for (int k = 0; k < 16; k++) {
        acc0 = fmaf(a[k], sW[k * 3 + 0], acc0);
        acc1 = fmaf(a[k], sW[k * 3 + 1], acc1);
        acc2 = fmaf(a[k], sW[k * 3 + 2], acc2);
    }
    float r0 = acc0 + sB[0], r1 = acc1 + sB[1], r2 = acc2 + sB[2];
    g_negx[n] = -(r0 > 0.f ? r0 : 0.f);
    g_negy[n] = -(r1 > 0.f ? r1 : 0.f);
    g_negz[n] = -(r2 > 0.f ? r2 : 0.f);
}

// ---------------- GEMM1 fused: h1 = relu(g_ax @ W1 + b1) ----------------
__global__ void k_gemm1f(const float* __restrict__ W1, const float* __restrict__ b1) {
    __shared__ float As[16][64];
    __shared__ float Bs[16][64];
    int tid = threadIdx.x;
    int bx = blockIdx.x, by = blockIdx.y;
    int tx = tid & 15, ty = tid >> 4;
    float acc[4][4];
#pragma unroll
    for (int i = 0; i < 4; i++)
#pragma unroll
        for (int j = 0; j < 4; j++) acc[i][j] = 0.f;
    int arow = tid >> 2, acol = (tid & 3) << 2;
    int brow = tid >> 4, bcol = (tid & 15) << 2;
    {
        float4 av = *(const float4*)(g_ax + (size_t)(by * 64 + arow) * INCH + acol);
        float4 bv = *(const float4*)(W1 + (size_t)brow * HIDD + bx * 64 + bcol);
        As[acol + 0][arow] = av.x; As[acol + 1][arow] = av.y;
        As[acol + 2][arow] = av.z; As[acol + 3][arow] = av.w;
        *(float4*)&Bs[brow][bcol] = bv;
        __syncthreads();
#pragma unroll
        for (int kk = 0; kk < 16; kk++) {
            float4 a = *(const float4*)&As[kk][ty << 2];
            float4 b = *(const float4*)&Bs[kk][tx << 2];
            float aa[4] = {a.x, a.y, a.z, a.w};
            float bb[4] = {b.x, b.y, b.z, b.w};
#pragma unroll
            for (int i = 0; i < 4; i++)
#pragma unroll
                for (int j = 0; j < 4; j++) acc[i][j] += aa[i] * bb[j];
        }
    }
    int col0 = bx * 64 + (tx << 2);
    float4 bv = *(const float4*)&b1[col0];
    float bb[4] = {bv.x, bv.y, bv.z, bv.w};
#pragma unroll
    for (int i = 0; i < 4; i++) {
        int row = by * 64 + (ty << 2) + i;
        float r[4];
#pragma unroll
        for (int j = 0; j < 4; j++) {
            float v = acc[i][j] + bb[j];
            r[j] = v > 0.f ? v : 0.f;
        }
        *(float4*)(g_h1 + (size_t)row * HIDD + col0) = make_float4(r[0], r[1], r[2], r[3]);
    }
}

// ---------------- KNN brute force, k=4, packed f32x2, lowest-index tie-break ----------------
__device__ __forceinline__ void ins4(float d2, int j,
                                     float& b0, float& b1, float& b2, float& b3,
                                     int& i0, int& i1, int& i2, int& i3) {
    if (d2 < b1) {
        b3 = b2; i3 = i2; b2 = b1; i2 = i1;
        if (d2 < b0) { b1 = b0; i1 = i0; b0 = d2; i0 = j; }
        else { b1 = d2; i1 = j; }
    } else {
        if (d2 < b2) { b3 = b2; i3 = i2; b2 = d2; i2 = j; }
        else { b3 = d2; i3 = j; }
    }
}

__global__ void k_knn() {
    __shared__ __align__(16) float sx[NN];
    __shared__ __align__(16) float sy[NN];
    __shared__ __align__(16) float sz[NN];
    __shared__ float md[256 * 4];
    __shared__ int   mi[256 * 4];
    int b = blockIdx.x >> 5;
    int chunk = blockIdx.x & 31;
    int tid = threadIdx.x;
    int gbase = b * NN;
    for (int j = tid; j < NN; j += 256) {
        sx[j] = g_negx[gbase + j];
        sy[j] = g_negy[gbase + j];
        sz[j] = g_negz[gbase + j];
    }
    __syncthreads();
    int ql = tid & 63;
    int sp = tid >> 6;
    int qi = chunk * 64 + ql;
    float qx = -sx[qi], qy = -sy[qi], qz = -sz[qi];
    unsigned long long qx2 = pack2(qx, qx);
    unsigned long long qy2 = pack2(qy, qy);
    unsigned long long qz2 = pack2(qz, qz);
    float b0 = 3.0e38f, b1 = 3.0e38f, b2 = 3.0e38f, b3 = 3.0e38f;
    int i0 = -1, i1 = -1, i2 = -1, i3 = -1;
    int j0 = sp * 512, j1 = j0 + 512;
    bool owns_qi = ((chunk >> 3) == sp);
    if (owns_qi) {
#pragma unroll 4
        for (int j = j0; j < j1; j += 2) {
            unsigned long long px = *(const unsigned long long*)(sx + j);
            unsigned long long py = *(const unsigned long long*)(sy + j);
            unsigned long long pz = *(const unsigned long long*)(sz + j);
            unsigned long long dx = add2(qx2, px);
            unsigned long long dy = add2(qy2, py);
            unsigned long long dz = add2(qz2, pz);
            unsigned long long d2p = add2(add2(mul2(dx, dx), mul2(dy, dy)), mul2(dz, dz));
            float dlo, dhi; unpack2(d2p, dlo, dhi);
            if (dlo < b3 && j != qi)       ins4(dlo, j,     b0, b1, b2, b3, i0, i1, i2, i3);
            if (dhi < b3 && (j + 1) != qi) ins4(dhi, j + 1, b0, b1, b2, b3, i0, i1, i2, i3);
        }
    } else {
#pragma unroll 4
        for (int j = j0; j < j1; j += 2) {
            unsigned long long px = *(const unsigned long long*)(sx + j);
            unsigned long long py = *(const unsigned long long*)(sy + j);
            unsigned long long pz = *(const unsigned long long*)(sz + j);
            unsigned long long dx = add2(qx2, px);
            unsigned long long dy = add2(qy2, py);
            unsigned long long dz = add2(qz2, pz);
            unsigned long long d2p = add2(add2(mul2(dx, dx), mul2(dy, dy)), mul2(dz, dz));
            float dlo, dhi; unpack2(d2p, dlo, dhi);
            if (dlo < b3) ins4(dlo, j,     b0, b1, b2, b3, i0, i1, i2, i3);
            if (dhi < b3) ins4(dhi, j + 1, b0, b1, b2, b3, i0, i1, i2, i3);
        }
    }
    md[tid * 4 + 0] = b0; md[tid * 4 + 1] = b1; md[tid * 4 + 2] = b2; md[tid * 4 + 3] = b3;
    mi[tid * 4 + 0] = i0; mi[tid * 4 + 1] = i1; mi[tid * 4 + 2] = i2; mi[tid * 4 + 3] = i3;
    __syncthreads();
    if (sp == 0) {
        int res[4];
        for (int r = 0; r < 4; r++) {
            float bd = 3.4e38f; int bi = 0x7fffffff; int bloc = -1;
            for (int s2 = 0; s2 < 4; s2++) {
                int base2 = (s2 * 64 + ql) * 4;
#pragma unroll
                for (int k = 0; k < 4; k++) {
                    float d = md[base2 + k]; int ii = mi[base2 + k];
                    if (d < bd || (d == bd && ii < bi)) { bd = d; bi = ii; bloc = base2 + k; }
                }
            }
            md[bloc] = 3.4e38f;
            res[r] = bi;
        }
        int4 o = make_int4(gbase + res[0], gbase + res[1], gbase + res[2], gbase + res[3]);
        *(int4*)&g_knn[(size_t)(gbase + qi) * 4] = o;
    }
}

// ---------------- tiled GEMM2: g_xw2 = h1 @ W2 ----------------
__global__ void k_gemm2(const float* __restrict__ W2) {
    __shared__ float As[16][64];
    __shared__ float Bs[16][64];
    int tid = threadIdx.x;
    int bx = blockIdx.x, by = blockIdx.y;
    int tx = tid & 15, ty = tid >> 4;
    float acc[4][4];
#pragma unroll
    for (int i = 0; i < 4; i++)
#pragma unroll
        for (int j = 0; j < 4; j++) acc[i][j] = 0.f;
    int arow = tid >> 2, acol = (tid & 3) << 2;
    int brow = tid >> 4, bcol = (tid & 15) << 2;
    const float* Ap = g_h1 + (size_t)(by * 64 + arow) * HIDD + acol;
    const float* Wq = W2 + (size_t)brow * HIDD + bx * 64 + bcol;
    for (int kt = 0; kt < HIDD; kt += 16) {
        float4 av = *(const float4*)(Ap + kt);
        float4 bv = *(const float4*)(Wq + (size_t)kt * HIDD);
        As[acol + 0][arow] = av.x; As[acol + 1][arow] = av.y;
        As[acol + 2][arow] = av.z; As[acol + 3][arow] = av.w;
        *(float4*)&Bs[brow][bcol] = bv;
        __syncthreads();
#pragma unroll
        for (int kk = 0; kk < 16; kk++) {
            float4 a = *(const float4*)&As[kk][ty << 2];
            float4 b = *(const float4*)&Bs[kk][tx << 2];
            float aa[4] = {a.x, a.y, a.z, a.w};
            float bb[4] = {b.x, b.y, b.z, b.w};
#pragma unroll
            for (int i = 0; i < 4; i++)
#pragma unroll
                for (int j = 0; j < 4; j++) acc[i][j] += aa[i] * bb[j];
        }
        __syncthreads();
    }
#pragma unroll
    for (int i = 0; i < 4; i++) {
        float4 v = make_float4(acc[i][0], acc[i][1], acc[i][2], acc[i][3]);
        *(float4*)(g_xw2 + (size_t)(by * 64 + (ty << 2) + i) * HIDD + bx * 64 + (tx << 2)) = v;
    }
}

// ---------------- GCN2: uniform degree 5, norm = 0.2 ----------------
__global__ void k_gcn2(const float* __restrict__ b2) {
    int n = blockIdx.x * 2 + (threadIdx.x >> 7);
    int t = threadIdx.x & 127;
    int4 nb = *(const int4*)&g_knn[(size_t)n * 4];
    float acc = g_xw2[(size_t)n * HIDD + t]
              + g_xw2[(size_t)nb.x * HIDD + t]
              + g_xw2[(size_t)nb.y * HIDD + t]
              + g_xw2[(size_t)nb.z * HIDD + t]
              + g_xw2[(size_t)nb.w * HIDD + t];
    float v = acc * 0.2f + b2[t];
    g_h2[(size_t)n * HIDD + t] = v > 0.f ? v : 0.f;
}

// ---------------- GEMM3 fused: s = softmax(h2 @ Wp + bp) ----------------
__global__ void k_gemm3s(const float* __restrict__ Wp, const float* __restrict__ bp,
                         float* __restrict__ dout, int limit) {
    __shared__ float As[16][64];
    __shared__ float Bs[16][64];
    int tid = threadIdx.x;
    int by = blockIdx.x;
    int tx = tid & 15, ty = tid >> 4;
    float acc[4][4];
#pragma unroll
    for (int i = 0; i < 4; i++)
#pragma unroll
        for (int j = 0; j < 4; j++) acc[i][j] = 0.f;
    int arow = tid >> 2, acol = (tid & 3) << 2;
    int brow = tid >> 4, bcol = (tid & 15) << 2;
    const float* Ap = g_h2 + (size_t)(by * 64 + arow) * HIDD + acol;
    const float* Wq = Wp + (size_t)brow * CC + bcol;
    for (int kt = 0; kt < HIDD; kt += 16) {
        float4 av = *(const float4*)(Ap + kt);
        float4 bv = *(const float4*)(Wq + (size_t)kt * CC);
        As[acol + 0][arow] = av.x; As[acol + 1][arow] = av.y;
        As[acol + 2][arow] = av.z; As[acol + 3][arow] = av.w;
        *(float4*)&Bs[brow][bcol] = bv;
        __syncthreads();
#pragma unroll
        for (int kk = 0; kk < 16; kk++) {
            float4 a = *(const float4*)&As[kk][ty << 2];
            float4 b = *(const float4*)&Bs[kk][tx << 2];
            float aa[4] = {a.x, a.y, a.z, a.w};
            float bb[4] = {b.x, b.y, b.z, b.w};
#pragma unroll
            for (int i = 0; i < 4; i++)
#pragma unroll
                for (int j = 0; j < 4; j++) acc[i][j] += aa[i] * bb[j];
        }
        __syncthreads();
    }
    float4 bv = *(const float4*)&bp[tx << 2];
    float bb[4] = {bv.x, bv.y, bv.z, bv.w};
#pragma unroll
    for (int i = 0; i < 4; i++) {
        float v[4];
#pragma unroll
        for (int j = 0; j < 4; j++) v[j] = acc[i][j] + bb[j];
        float m = fmaxf(fmaxf(v[0], v[1]), fmaxf(v[2], v[3]));
#pragma unroll
        for (int o = 8; o > 0; o >>= 1) m = fmaxf(m, __shfl_xor_sync(0xffffffffu, m, o));
        float e[4]; float sum = 0.f;
#pragma unroll
        for (int j = 0; j < 4; j++) { e[j] = expf(v[j] - m); sum += e[j]; }
#pragma unroll
        for (int o = 8; o > 0; o >>= 1) sum += __shfl_xor_sync(0xffffffffu, sum, o);
        float inv = 1.f / sum;
#pragma unroll
        for (int j = 0; j < 4; j++) e[j] *= inv;
        int row = by * 64 + (ty << 2) + i;
        *(float4*)(g_s + (size_t)row * CC + (tx << 2)) = make_float4(e[0], e[1], e[2], e[3]);
        int base = 65537 + row * CC + (tx << 2);
#pragma unroll
        for (int j = 0; j < 4; j++)
            if (base + j < limit) dout[base + j] = e[j];
    }
}

// ---- AS gather + trace(S^T A S) ----
__global__ void k_asgather() {
    __shared__ float str;
    int n = blockIdx.x * 4 + (threadIdx.x >> 6);
    int t = threadIdx.x & 63;
    if (threadIdx.x == 0) str = 0.f;
    __syncthreads();
    int beg = g_off_src[n], end = g_off_src[n + 1];
    float acc = 0.f;
    for (int e = beg; e < end; e++) {
        int j = g_e_by_src[e];
        acc += g_s[(size_t)j * CC + t];
    }
    g_AS[(size_t)n * CC + t] = acc;
    float c = acc * g_s[(size_t)n * CC + t];
#pragma unroll
    for (int o = 16; o > 0; o >>= 1) c += __shfl_xor_sync(0xffffffffu, c, o);
    if ((threadIdx.x & 31) == 0) atomicAdd(&str, c);
    __syncthreads();
    if (threadIdx.x == 0) atomicAdd(&g_tr[blockIdx.x >> 9], str);
}

// ---- fused per-graph: ss = S^T S, pool = S^T X, ca/colsum ----
__global__ void k_reduce1() {
    __shared__ float sS[4][64], sX[4][128], sD[4];
    int b = blockIdx.x >> 4;
    int chunk = blockIdx.x & 15;
    int tid = threadIdx.x;
    int c = tid >> 2, qq = tid & 3;
    int d0 = qq * 16, f0 = qq * 32;
    float ass[16], aout[32];
#pragma unroll
    for (int k = 0; k < 16; k++) ass[k] = 0.f;
#pragma unroll
    for (int k = 0; k < 32; k++) aout[k] = 0.f;
    float csum = 0.f, casum = 0.f;
    int node0 = b * NN + chunk * 128;
    for (int nb = 0; nb < 128; nb += 4) {
        {
            int nn2 = tid >> 6, cc2 = tid & 63;
            int node = node0 + nb + nn2;
            sS[nn2][cc2] = g_s[(size_t)node * CC + cc2];
        }
        if (tid < 4) sD[tid] = g_degf[node0 + nb + tid];
        for (int u = tid; u < 4 * 128; u += 256) {
            int nn2 = u >> 7, ff = u & 127;
            int node = node0 + nb + nn2;
            sX[nn2][ff] = g_h2[(size_t)node * HIDD + ff];
        }
        __syncthreads();
#pragma unroll
        for (int nn2 = 0; nn2 < 4; nn2++) {
            float sa = sS[nn2][c];
#pragma unroll
            for (int k = 0; k < 16; k++) ass[k] += sa * sS[nn2][d0 + k];
#pragma unroll
            for (int k = 0; k < 32; k++) aout[k] += sa * sX[nn2][f0 + k];
            if (qq == 0) { csum += sa; casum += sa * sD[nn2]; }
        }
        __syncthreads();
    }
#pragma unroll
    for (int k = 0; k < 16; k++)
        atomicAdd(&g_ssm[b * CC * CC + c * CC + d0 + k], ass[k]);
#pragma unroll
    for (int k = 0; k < 32; k++)
        atomicAdd(&g_pool[b * CC * HIDD + c * HIDD + f0 + k], aout[k]);
    if (qq == 0) {
        atomicAdd(&g_colsum[b * CC + c], csum);
        atomicAdd(&g_ca[b * CC + c], casum);
    }
}

// ---------------- losses: one block per graph ----------------
__device__ __forceinline__ float blockReduceSum256(float v, float* sh) {
    sh[threadIdx.x] = v; __syncthreads();
    for (int s = 128; s > 0; s >>= 1) {
        if (threadIdx.x < s) sh[threadIdx.x] += sh[threadIdx.x + s];
        __syncthreads();
    }
    float r = sh[0]; __syncthreads();
    return r;
}

__global__ void k_loss() {
    __shared__ float sh[256];
    int t = threadIdx.x;
    int b = blockIdx.x;
    const float* ss = g_ssm + b * CC * CC;
    float v = 0.f;
    for (int i = t; i < CC * CC; i += 256) { float w = ss[i]; v += w * w; }
    float fro = sqrtf(blockReduceSum256(v, sh));
    v = 0.f;
    for (int i = t; i < CC * CC; i += 256) {
        float w = ss[i] / fro - ((i % (CC + 1)) == 0 ? 0.125f : 0.f);
        v += w * w;
    }
    float ortho_b = sqrtf(blockReduceSum256(v, sh));
    v = (t < CC) ? g_ca[b * CC + t] * g_ca[b * CC + t] : 0.f;
    float ca2 = blockReduceSum256(v, sh);
    v = (t < CC) ? g_colsum[b * CC + t] * g_colsum[b * CC + t] : 0.f;
    float cs2 = blockReduceSum256(v, sh);
    v = 0.f;
    for (int n = t; n < NN; n += 256) v += g_degf[b * NN + n];
    float twom = blockReduceSum256(v, sh);
    float tr = g_tr[b];
    float spectral_b = -(tr - ca2 / twom) / twom;
    float cluster_b = sqrtf(cs2) / (float)NN * 8.0f - 1.0f;
    if (t == 0) g_lossb[b] = spectral_b + ortho_b + cluster_b;
}

// ---------------- selu + log_softmax + loss combine ----------------
__global__ void k_selulsm(float* __restrict__ dout, int limit) {
    int row = (blockIdx.x * 256 + threadIdx.x) >> 5;
    int lane = threadIdx.x & 31;
    float4 p = *(const float4*)&g_pool[(size_t)row * HIDD + lane * 4];
    const float SC = 1.0507009873554805f, AL = 1.6732632423543772f;
    float y[4] = {p.x, p.y, p.z, p.w};
#pragma unroll
    for (int k = 0; k < 4; k++) y[k] = y[k] > 0.f ? SC * y[k] : SC * (AL * expm1f(y[k]));
    float mx = fmaxf(fmaxf(y[0], y[1]), fmaxf(y[2], y[3]));
#pragma unroll
    for (int o = 16; o > 0; o >>= 1) mx = fmaxf(mx, __shfl_xor_sync(0xffffffffu, mx, o));
    float sum = 0.f;
#pragma unroll
    for (int k = 0; k < 4; k++) sum += expf(y[k] - mx);
#pragma unroll
    for (int o = 16; o > 0; o >>= 1) sum += __shfl_xor_sync(0xffffffffu, sum, o);
    float lse = logf(sum) + mx;
    int base = row * HIDD + lane * 4;
    if (base + 3 < limit) {
        float4 o4 = make_float4(y[0] - lse, y[1] - lse, y[2] - lse, y[3] - lse);
        *(float4*)&dout[base] = o4;
    }
    if (blockIdx.x == 0 && threadIdx.x == 0 && 65536 < limit) {
        float tot = 0.f;
#pragma unroll
        for (int i = 0; i < BB; i++) tot += g_lossb[i];
        dout[65536] = tot * 0.125f;
    }
}

// ---------------- launcher: 2-stream DAG ----------------
extern "C" void kernel_launch(void* const* d_in, const int* in_sizes, int n_in,
                              void* d_out, int out_size) {
    const float* x    = (const float*)d_in[0];
    const int*   esrc = (const int*)d_in[1];
    const int*   edst = (const int*)d_in[2];
    const float* W1 = (const float*)d_in[4];
    const float* b1 = (const float*)d_in[5];
    const float* W2 = (const float*)d_in[6];
    const float* b2 = (const float*)d_in[7];
    const float* Wp = (const float*)d_in[8];
    const float* bp = (const float*)d_in[9];
    float* out = (float*)d_out;

    static cudaStream_t s1 = nullptr;
    static cudaEvent_t evI, evA, evB, evC, evD, evS;
    if (!s1) {
        cudaStreamCreateWithFlags(&s1, cudaStreamNonBlocking);
        cudaEventCreateWithFlags(&evI, cudaEventDisableTiming);
        cudaEventCreateWithFlags(&evA, cudaEventDisableTiming);
        cudaEventCreateWithFlags(&evB, cudaEventDisableTiming);
        cudaEventCreateWithFlags(&evC, cudaEventDisableTiming);
        cudaEventCreateWithFlags(&evD, cudaEventDisableTiming);
        cudaEventCreateWithFlags(&evS, cudaEventDisableTiming);
    }

    // main stream: critical path
    k_init<<<256, 256>>>();
    cudaEventRecord(evI, 0);

    // side stream: src-CSR lane (consumed only by asgather)
    cudaStreamWaitEvent(s1, evI, 0);
    k_count_src<<<EE / 256, 256, 0, s1>>>(esrc);
    k_scan_src<<<1, 1024, 0, s1>>>();
    k_fill_src<<<EE / 256, 256, 0, s1>>>(esrc, edst);
    cudaEventRecord(evS, s1);

    // main: dst-CSR -> aggx
    k_count_dst<<<EE / 256, 256>>>(esrc, edst);
    k_scan_dst<<<2, 1024>>>();
    k_fill_dst<<<EE / 256, 256>>>(esrc, edst);
    k_aggx<<<BN / 16, 256>>>(x);
    cudaEventRecord(evA, 0);

    // side stream: full GEMM lane (h1, xw2) overlapped with KNN
    cudaStreamWaitEvent(s1, evA, 0);
    k_gemm1f<<<dim3(2, 256), 256, 0, s1>>>(W1, b1);
    k_gemm2<<<dim3(2, 256), 256, 0, s1>>>(W2);
    cudaEventRecord(evB, s1);

    // main: coords -> knn
    k_coord3<<<BN / 256, 256>>>(W1, b1);
    k_knn<<<256, 256>>>();
    cudaStreamWaitEvent(0, evB, 0);
    k_gcn2<<<BN / 2, 256>>>(b2);
    k_gemm3s<<<256, 256>>>(Wp, bp, out, out_size);
    cudaEventRecord(evC, 0);

    // side stream: reduce1 overlapped with asgather
    cudaStreamWaitEvent(s1, evC, 0);
    k_reduce1<<<128, 256, 0, s1>>>();
    cudaEventRecord(evD, s1);

    // main: asgather (needs src CSR) -> loss -> epilogue
    cudaStreamWaitEvent(0, evS, 0);
    k_asgather<<<BN / 4, 256>>>();
    cudaStreamWaitEvent(0, evD, 0);
    k_loss<<<BB, 256>>>();
    k_selulsm<<<BB * CC / 8, 256>>>(out, out_size);
}